// round 2
// baseline (speedup 1.0000x reference)
#include <cuda_runtime.h>
#include <cstdint>

// Problem constants
#define Bv 16
#define Nv 576
#define Cv 768
#define Hv 12
#define HDv 64
#define BH (Bv*Hv)            // 192
#define MROWS (Bv*Nv)         // 9216

// Scratch (device globals; no allocation allowed)
__device__ float g_q[BH * Nv * HDv];     // (b,h,n,d)
__device__ float g_k[BH * Nv * HDv];
__device__ float g_v[BH * Nv * HDv];
__device__ float g_S[(size_t)BH * Nv * Nv];      // scores / mixed probs, (b,h,m,n)
__device__ float g_O[MROWS * Cv];                // (b,n, h*64+d)

// ---------------------------------------------------------------------------
// 64x64x16 fp32 tile GEMM core pieces (A row-major MxK, W row-major NcxK -> A@W^T)
// 256 threads, 4x4 per thread.
// ---------------------------------------------------------------------------

// Kernel 1: qkv = x @ Wqkv^T, scattered into g_q/g_k/g_v with q*0.125
__global__ __launch_bounds__(256) void qkv_gemm_kernel(const float* __restrict__ X,
                                                       const float* __restrict__ W) {
    __shared__ float As[16][64];
    __shared__ float Bs[16][64];
    const int K = Cv;
    const int m0 = blockIdx.y * 64;
    const int n0 = blockIdx.x * 64;
    const int tid = threadIdx.x;
    const int tx = tid & 15, ty = tid >> 4;
    const int lr = tid >> 2, lc = (tid & 3) << 2;

    float acc[4][4];
#pragma unroll
    for (int i = 0; i < 4; i++)
#pragma unroll
        for (int j = 0; j < 4; j++) acc[i][j] = 0.f;

    for (int kb = 0; kb < K; kb += 16) {
        float4 a = *(const float4*)(X + (size_t)(m0 + lr) * K + kb + lc);
        float4 b = *(const float4*)(W + (size_t)(n0 + lr) * K + kb + lc);
        As[lc + 0][lr] = a.x; As[lc + 1][lr] = a.y; As[lc + 2][lr] = a.z; As[lc + 3][lr] = a.w;
        Bs[lc + 0][lr] = b.x; Bs[lc + 1][lr] = b.y; Bs[lc + 2][lr] = b.z; Bs[lc + 3][lr] = b.w;
        __syncthreads();
#pragma unroll
        for (int k = 0; k < 16; k++) {
            float4 av = *(const float4*)&As[k][ty << 2];
            float4 bv = *(const float4*)&Bs[k][tx << 2];
            acc[0][0] += av.x * bv.x; acc[0][1] += av.x * bv.y; acc[0][2] += av.x * bv.z; acc[0][3] += av.x * bv.w;
            acc[1][0] += av.y * bv.x; acc[1][1] += av.y * bv.y; acc[1][2] += av.y * bv.z; acc[1][3] += av.y * bv.w;
            acc[2][0] += av.z * bv.x; acc[2][1] += av.z * bv.y; acc[2][2] += av.z * bv.z; acc[2][3] += av.z * bv.w;
            acc[3][0] += av.w * bv.x; acc[3][1] += av.w * bv.y; acc[3][2] += av.w * bv.z; acc[3][3] += av.w * bv.w;
        }
        __syncthreads();
    }

    // epilogue: n0 is a multiple of 64 -> (t, h) constant over the tile, d = tx*4+jj
    const int t = n0 / Cv;
    const int h = (n0 % Cv) >> 6;
    float* dst = (t == 0) ? g_q : (t == 1) ? g_k : g_v;
    const float scale = (t == 0) ? 0.125f : 1.0f;
#pragma unroll
    for (int i = 0; i < 4; i++) {
        int r = m0 + (ty << 2) + i;
        int b = r / Nv, n = r % Nv;
        float4 v4 = make_float4(acc[i][0] * scale, acc[i][1] * scale, acc[i][2] * scale, acc[i][3] * scale);
        *(float4*)&dst[(((size_t)b * Hv + h) * Nv + n) * HDv + (tx << 2)] = v4;
    }
}

// Kernel 2: S[bh] = q[bh] (576x64) @ k[bh]^T
__global__ __launch_bounds__(256) void scores_gemm_kernel() {
    __shared__ float As[16][64];
    __shared__ float Bs[16][64];
    const int K = HDv;
    const int bh = blockIdx.z;
    const int m0 = blockIdx.x * 64;
    const int n0 = blockIdx.y * 64;
    const float* __restrict__ X = g_q + (size_t)bh * Nv * HDv;
    const float* __restrict__ W = g_k + (size_t)bh * Nv * HDv;
    const int tid = threadIdx.x;
    const int tx = tid & 15, ty = tid >> 4;
    const int lr = tid >> 2, lc = (tid & 3) << 2;

    float acc[4][4];
#pragma unroll
    for (int i = 0; i < 4; i++)
#pragma unroll
        for (int j = 0; j < 4; j++) acc[i][j] = 0.f;

    for (int kb = 0; kb < K; kb += 16) {
        float4 a = *(const float4*)(X + (size_t)(m0 + lr) * K + kb + lc);
        float4 b = *(const float4*)(W + (size_t)(n0 + lr) * K + kb + lc);
        As[lc + 0][lr] = a.x; As[lc + 1][lr] = a.y; As[lc + 2][lr] = a.z; As[lc + 3][lr] = a.w;
        Bs[lc + 0][lr] = b.x; Bs[lc + 1][lr] = b.y; Bs[lc + 2][lr] = b.z; Bs[lc + 3][lr] = b.w;
        __syncthreads();
#pragma unroll
        for (int k = 0; k < 16; k++) {
            float4 av = *(const float4*)&As[k][ty << 2];
            float4 bv = *(const float4*)&Bs[k][tx << 2];
            acc[0][0] += av.x * bv.x; acc[0][1] += av.x * bv.y; acc[0][2] += av.x * bv.z; acc[0][3] += av.x * bv.w;
            acc[1][0] += av.y * bv.x; acc[1][1] += av.y * bv.y; acc[1][2] += av.y * bv.z; acc[1][3] += av.y * bv.w;
            acc[2][0] += av.z * bv.x; acc[2][1] += av.z * bv.y; acc[2][2] += av.z * bv.z; acc[2][3] += av.z * bv.w;
            acc[3][0] += av.w * bv.x; acc[3][1] += av.w * bv.y; acc[3][2] += av.w * bv.z; acc[3][3] += av.w * bv.w;
        }
        __syncthreads();
    }

    float* Sp = g_S + (size_t)bh * Nv * Nv;
#pragma unroll
    for (int i = 0; i < 4; i++) {
        int r = m0 + (ty << 2) + i;
        *(float4*)&Sp[(size_t)r * Nv + n0 + (tx << 2)] =
            make_float4(acc[i][0], acc[i][1], acc[i][2], acc[i][3]);
    }
}

// Kernel 3: per (b,m): pre-mix (Wl,bl) over heads -> softmax over n -> post-mix (Ww,bw), in place.
// 576 threads: thread t owns column n=t. 12 warps handle the 12 per-head softmaxes.
__global__ __launch_bounds__(576) void mix_softmax_kernel(const float* __restrict__ Wl,
                                                          const float* __restrict__ bl,
                                                          const float* __restrict__ Ww,
                                                          const float* __restrict__ bw) {
    __shared__ float Ls[Hv][Nv];
    __shared__ float wl_s[Hv * Hv], ww_s[Hv * Hv], bl_s[Hv], bw_s[Hv];
    const int m = blockIdx.x;
    const int b = blockIdx.y;
    const int tid = threadIdx.x;

    if (tid < Hv * Hv) { wl_s[tid] = Wl[tid]; ww_s[tid] = Ww[tid]; }
    if (tid < Hv) { bl_s[tid] = bl[tid]; bw_s[tid] = bw[tid]; }
    __syncthreads();

    // pre-mix: L[g][t] = bl[g] + sum_h Wl[g,h] * S[b,h,m,t]
    float L[Hv];
#pragma unroll
    for (int g = 0; g < Hv; g++) L[g] = bl_s[g];
#pragma unroll
    for (int h = 0; h < Hv; h++) {
        float sval = g_S[(((size_t)b * Hv + h) * Nv + m) * Nv + tid];
#pragma unroll
        for (int g = 0; g < Hv; g++) L[g] += wl_s[g * Hv + h] * sval;
    }
#pragma unroll
    for (int g = 0; g < Hv; g++) Ls[g][tid] = L[g];
    __syncthreads();

    // softmax per head: warp w handles head w
    const int w = tid >> 5, lane = tid & 31;
    if (w < Hv) {
        float mx = -1e30f;
        for (int n = lane; n < Nv; n += 32) mx = fmaxf(mx, Ls[w][n]);
#pragma unroll
        for (int o = 16; o; o >>= 1) mx = fmaxf(mx, __shfl_xor_sync(0xffffffffu, mx, o));
        float s = 0.f;
        for (int n = lane; n < Nv; n += 32) {
            float e = __expf(Ls[w][n] - mx);
            Ls[w][n] = e;
            s += e;
        }
#pragma unroll
        for (int o = 16; o; o >>= 1) s += __shfl_xor_sync(0xffffffffu, s, o);
        float inv = 1.f / s;
        for (int n = lane; n < Nv; n += 32) Ls[w][n] *= inv;
    }
    __syncthreads();

    // post-mix: P'[g][t] = bw[g] + sum_h Ww[g,h] * P[h][t]; write back to g_S
    float p[Hv];
#pragma unroll
    for (int h = 0; h < Hv; h++) p[h] = Ls[h][tid];
#pragma unroll
    for (int g = 0; g < Hv; g++) {
        float a = bw_s[g];
#pragma unroll
        for (int h = 0; h < Hv; h++) a += ww_s[g * Hv + h] * p[h];
        g_S[(((size_t)b * Hv + g) * Nv + m) * Nv + tid] = a;
    }
}

// Kernel 4: O[bh] = P'[bh] (576x576) @ V[bh] (576x64), written as (b, m, h*64+d)
__global__ __launch_bounds__(256) void pv_gemm_kernel() {
    __shared__ float As[16][64];
    __shared__ float Bs[16][64];
    const int bh = blockIdx.z;
    const int m0 = blockIdx.x * 64;
    const float* __restrict__ A = g_S + (size_t)bh * Nv * Nv;   // 576x576
    const float* __restrict__ Bp = g_v + (size_t)bh * Nv * HDv; // 576x64, k-major rows
    const int tid = threadIdx.x;
    const int tx = tid & 15, ty = tid >> 4;
    const int lr = tid >> 2, lc = (tid & 3) << 2;
    const int kr = tid >> 4, kc = (tid & 15) << 2;

    float acc[4][4];
#pragma unroll
    for (int i = 0; i < 4; i++)
#pragma unroll
        for (int j = 0; j < 4; j++) acc[i][j] = 0.f;

    for (int kb = 0; kb < Nv; kb += 16) {
        float4 a = *(const float4*)(A + (size_t)(m0 + lr) * Nv + kb + lc);
        float4 b = *(const float4*)(Bp + (size_t)(kb + kr) * HDv + kc);
        As[lc + 0][lr] = a.x; As[lc + 1][lr] = a.y; As[lc + 2][lr] = a.z; As[lc + 3][lr] = a.w;
        *(float4*)&Bs[kr][kc] = b;
        __syncthreads();
#pragma unroll
        for (int k = 0; k < 16; k++) {
            float4 av = *(const float4*)&As[k][ty << 2];
            float4 bv = *(const float4*)&Bs[k][tx << 2];
            acc[0][0] += av.x * bv.x; acc[0][1] += av.x * bv.y; acc[0][2] += av.x * bv.z; acc[0][3] += av.x * bv.w;
            acc[1][0] += av.y * bv.x; acc[1][1] += av.y * bv.y; acc[1][2] += av.y * bv.z; acc[1][3] += av.y * bv.w;
            acc[2][0] += av.z * bv.x; acc[2][1] += av.z * bv.y; acc[2][2] += av.z * bv.z; acc[2][3] += av.z * bv.w;
            acc[3][0] += av.w * bv.x; acc[3][1] += av.w * bv.y; acc[3][2] += av.w * bv.z; acc[3][3] += av.w * bv.w;
        }
        __syncthreads();
    }

    const int b = bh / Hv, h = bh % Hv;
#pragma unroll
    for (int i = 0; i < 4; i++) {
        int m = m0 + (ty << 2) + i;
        *(float4*)&g_O[((size_t)b * Nv + m) * Cv + h * HDv + (tx << 2)] =
            make_float4(acc[i][0], acc[i][1], acc[i][2], acc[i][3]);
    }
}

// Kernel 5: out = O (9216x768) @ Wproj^T + bproj
__global__ __launch_bounds__(256) void proj_gemm_kernel(const float* __restrict__ W,
                                                        const float* __restrict__ bias,
                                                        float* __restrict__ Y) {
    __shared__ float As[16][64];
    __shared__ float Bs[16][64];
    const int K = Cv;
    const int m0 = blockIdx.y * 64;
    const int n0 = blockIdx.x * 64;
    const float* __restrict__ X = g_O;
    const int tid = threadIdx.x;
    const int tx = tid & 15, ty = tid >> 4;
    const int lr = tid >> 2, lc = (tid & 3) << 2;

    float acc[4][4];
#pragma unroll
    for (int i = 0; i < 4; i++)
#pragma unroll
        for (int j = 0; j < 4; j++) acc[i][j] = 0.f;

    for (int kb = 0; kb < K; kb += 16) {
        float4 a = *(const float4*)(X + (size_t)(m0 + lr) * K + kb + lc);
        float4 b = *(const float4*)(W + (size_t)(n0 + lr) * K + kb + lc);
        As[lc + 0][lr] = a.x; As[lc + 1][lr] = a.y; As[lc + 2][lr] = a.z; As[lc + 3][lr] = a.w;
        Bs[lc + 0][lr] = b.x; Bs[lc + 1][lr] = b.y; Bs[lc + 2][lr] = b.z; Bs[lc + 3][lr] = b.w;
        __syncthreads();
#pragma unroll
        for (int k = 0; k < 16; k++) {
            float4 av = *(const float4*)&As[k][ty << 2];
            float4 bv = *(const float4*)&Bs[k][tx << 2];
            acc[0][0] += av.x * bv.x; acc[0][1] += av.x * bv.y; acc[0][2] += av.x * bv.z; acc[0][3] += av.x * bv.w;
            acc[1][0] += av.y * bv.x; acc[1][1] += av.y * bv.y; acc[1][2] += av.y * bv.z; acc[1][3] += av.y * bv.w;
            acc[2][0] += av.z * bv.x; acc[2][1] += av.z * bv.y; acc[2][2] += av.z * bv.z; acc[2][3] += av.z * bv.w;
            acc[3][0] += av.w * bv.x; acc[3][1] += av.w * bv.y; acc[3][2] += av.w * bv.z; acc[3][3] += av.w * bv.w;
        }
        __syncthreads();
    }

    const int jb = n0 + (tx << 2);
    float4 bi = *(const float4*)&bias[jb];
#pragma unroll
    for (int i = 0; i < 4; i++) {
        int r = m0 + (ty << 2) + i;
        *(float4*)&Y[(size_t)r * Cv + jb] =
            make_float4(acc[i][0] + bi.x, acc[i][1] + bi.y, acc[i][2] + bi.z, acc[i][3] + bi.w);
    }
}

extern "C" void kernel_launch(void* const* d_in, const int* in_sizes, int n_in,
                              void* d_out, int out_size) {
    const float* x     = (const float*)d_in[0];
    const float* Wqkv  = (const float*)d_in[1];
    const float* Wl    = (const float*)d_in[2];
    const float* bl    = (const float*)d_in[3];
    const float* Ww    = (const float*)d_in[4];
    const float* bw    = (const float*)d_in[5];
    const float* Wproj = (const float*)d_in[6];
    const float* bproj = (const float*)d_in[7];
    float* out = (float*)d_out;

    // 1) qkv projection -> g_q (scaled), g_k, g_v
    qkv_gemm_kernel<<<dim3(3 * Cv / 64, MROWS / 64), 256>>>(x, Wqkv);
    // 2) scores S = q @ k^T per (b,h)
    scores_gemm_kernel<<<dim3(Nv / 64, Nv / 64, BH), 256>>>();
    // 3) head-mix -> softmax -> head-mix (in place on g_S)
    mix_softmax_kernel<<<dim3(Nv, Bv), Nv>>>(Wl, bl, Ww, bw);
    // 4) O = P' @ V  -> (B,N,C) layout
    pv_gemm_kernel<<<dim3(Nv / 64, 1, BH), 256>>>();
    // 5) output projection + bias
    proj_gemm_kernel<<<dim3(Cv / 64, MROWS / 64), 256>>>(Wproj, bproj, out);
}

// round 3
// speedup vs baseline: 1.3306x; 1.3306x over previous
#include <cuda_runtime.h>
#include <cstdint>

// Problem constants
#define Bv 16
#define Nv 576
#define Cv 768
#define Hv 12
#define HDv 64
#define BH (Bv*Hv)            // 192
#define MROWS (Bv*Nv)         // 9216

// Scratch (device globals; no allocation allowed)
__device__ float g_q[BH * Nv * HDv];     // (b,h,n,d)
__device__ float g_k[BH * Nv * HDv];
__device__ float g_v[BH * Nv * HDv];
__device__ float g_S[(size_t)BH * Nv * Nv];      // scores / mixed probs, (b,h,m,n)
__device__ float g_O[MROWS * Cv];                // (b,n, h*64+d)

#define SW 132   // padded smem row width (floats), 16B-aligned, kills STS bank conflicts

// ---------------------------------------------------------------------------
// 128x128x8 fp32 GEMM (A row-major MxK) @ (W row-major NxK)^T, 256 threads,
// 8x8 per thread in 2x2 float4 sub-blocks. Used by qkv / scores / proj.
// ---------------------------------------------------------------------------

#define GEMM_CORE_DECL                                                         \
    __shared__ float As[8][SW];                                                \
    __shared__ float Bs[8][SW];                                                \
    const int tid = threadIdx.x;                                               \
    const int tx = tid & 15, ty = tid >> 4;                                    \
    const int ar = tid >> 1, ac = (tid & 1) << 2;                              \
    float acc[8][8];                                                           \
    _Pragma("unroll") for (int i = 0; i < 8; i++)                              \
        _Pragma("unroll") for (int j = 0; j < 8; j++) acc[i][j] = 0.f;

#define GEMM_COMPUTE_CHUNK                                                     \
    _Pragma("unroll")                                                          \
    for (int k = 0; k < 8; k++) {                                              \
        float4 a0 = *(const float4*)&As[k][ty << 2];                           \
        float4 a1 = *(const float4*)&As[k][64 + (ty << 2)];                    \
        float4 b0 = *(const float4*)&Bs[k][tx << 2];                           \
        float4 b1 = *(const float4*)&Bs[k][64 + (tx << 2)];                    \
        float av[8] = {a0.x, a0.y, a0.z, a0.w, a1.x, a1.y, a1.z, a1.w};        \
        float bv[8] = {b0.x, b0.y, b0.z, b0.w, b1.x, b1.y, b1.z, b1.w};        \
        _Pragma("unroll") for (int i = 0; i < 8; i++)                          \
            _Pragma("unroll") for (int j = 0; j < 8; j++)                      \
                acc[i][j] += av[i] * bv[j];                                    \
    }

// Kernel 1: qkv = x @ Wqkv^T, scattered into g_q/g_k/g_v with q*0.125
__global__ __launch_bounds__(256) void qkv_gemm_kernel(const float* __restrict__ X,
                                                       const float* __restrict__ W) {
    GEMM_CORE_DECL
    const int K = Cv;
    const int m0 = blockIdx.y << 7;
    const int n0 = blockIdx.x << 7;

    float4 aReg = *(const float4*)(X + (size_t)(m0 + ar) * K + ac);
    float4 bReg = *(const float4*)(W + (size_t)(n0 + ar) * K + ac);
    for (int kb = 0; kb < K; kb += 8) {
        __syncthreads();
        As[ac + 0][ar] = aReg.x; As[ac + 1][ar] = aReg.y; As[ac + 2][ar] = aReg.z; As[ac + 3][ar] = aReg.w;
        Bs[ac + 0][ar] = bReg.x; Bs[ac + 1][ar] = bReg.y; Bs[ac + 2][ar] = bReg.z; Bs[ac + 3][ar] = bReg.w;
        __syncthreads();
        if (kb + 8 < K) {
            aReg = *(const float4*)(X + (size_t)(m0 + ar) * K + kb + 8 + ac);
            bReg = *(const float4*)(W + (size_t)(n0 + ar) * K + kb + 8 + ac);
        }
        GEMM_COMPUTE_CHUNK
    }

#pragma unroll
    for (int g = 0; g < 2; g++) {
        const int jb = n0 + (g << 6) + (tx << 2);
        const int t = jb / Cv;
        const int rem = jb % Cv;
        const int h = rem >> 6, d = rem & 63;
        float* dst = (t == 0) ? g_q : (t == 1) ? g_k : g_v;
        const float scale = (t == 0) ? 0.125f : 1.0f;
#pragma unroll
        for (int i = 0; i < 8; i++) {
            const int r = m0 + ((i < 4) ? (ty << 2) + i : 64 + (ty << 2) + i - 4);
            const int b = r / Nv, n = r % Nv;
            *(float4*)&dst[(((size_t)b * Hv + h) * Nv + n) * HDv + d] =
                make_float4(acc[i][g*4+0] * scale, acc[i][g*4+1] * scale,
                            acc[i][g*4+2] * scale, acc[i][g*4+3] * scale);
        }
    }
}

// Kernel 2: S[bh] = q[bh] (576x64) @ k[bh]^T  (guarded 128x128 tiles)
__global__ __launch_bounds__(256) void scores_gemm_kernel() {
    GEMM_CORE_DECL
    const int K = HDv;
    const int bh = blockIdx.z;
    const int m0 = blockIdx.x << 7;
    const int n0 = blockIdx.y << 7;
    const float* __restrict__ X = g_q + (size_t)bh * Nv * HDv;
    const float* __restrict__ W = g_k + (size_t)bh * Nv * HDv;

    const int rmA = min(m0 + ar, Nv - 1);
    const int rmB = min(n0 + ar, Nv - 1);
    float4 aReg = *(const float4*)(X + (size_t)rmA * K + ac);
    float4 bReg = *(const float4*)(W + (size_t)rmB * K + ac);
    for (int kb = 0; kb < K; kb += 8) {
        __syncthreads();
        As[ac + 0][ar] = aReg.x; As[ac + 1][ar] = aReg.y; As[ac + 2][ar] = aReg.z; As[ac + 3][ar] = aReg.w;
        Bs[ac + 0][ar] = bReg.x; Bs[ac + 1][ar] = bReg.y; Bs[ac + 2][ar] = bReg.z; Bs[ac + 3][ar] = bReg.w;
        __syncthreads();
        if (kb + 8 < K) {
            aReg = *(const float4*)(X + (size_t)rmA * K + kb + 8 + ac);
            bReg = *(const float4*)(W + (size_t)rmB * K + kb + 8 + ac);
        }
        GEMM_COMPUTE_CHUNK
    }

    float* Sp = g_S + (size_t)bh * Nv * Nv;
#pragma unroll
    for (int g = 0; g < 2; g++) {
        const int c = n0 + (g << 6) + (tx << 2);
        if (c >= Nv) continue;
#pragma unroll
        for (int i = 0; i < 8; i++) {
            const int r = m0 + ((i < 4) ? (ty << 2) + i : 64 + (ty << 2) + i - 4);
            if (r >= Nv) continue;
            *(float4*)&Sp[(size_t)r * Nv + c] =
                make_float4(acc[i][g*4+0], acc[i][g*4+1], acc[i][g*4+2], acc[i][g*4+3]);
        }
    }
}

// Kernel 3: per (b,m): pre-mix (Wl,bl) over heads -> softmax over n -> post-mix (Ww,bw)
__global__ __launch_bounds__(576) void mix_softmax_kernel(const float* __restrict__ Wl,
                                                          const float* __restrict__ bl,
                                                          const float* __restrict__ Ww,
                                                          const float* __restrict__ bw) {
    __shared__ float Ls[Hv][Nv];
    __shared__ float wl_s[Hv * Hv], ww_s[Hv * Hv], bl_s[Hv], bw_s[Hv];
    const int m = blockIdx.x;
    const int b = blockIdx.y;
    const int tid = threadIdx.x;

    if (tid < Hv * Hv) { wl_s[tid] = Wl[tid]; ww_s[tid] = Ww[tid]; }
    if (tid < Hv) { bl_s[tid] = bl[tid]; bw_s[tid] = bw[tid]; }
    __syncthreads();

    float L[Hv];
#pragma unroll
    for (int g = 0; g < Hv; g++) L[g] = bl_s[g];
#pragma unroll
    for (int h = 0; h < Hv; h++) {
        float sval = g_S[(((size_t)b * Hv + h) * Nv + m) * Nv + tid];
#pragma unroll
        for (int g = 0; g < Hv; g++) L[g] += wl_s[g * Hv + h] * sval;
    }
#pragma unroll
    for (int g = 0; g < Hv; g++) Ls[g][tid] = L[g];
    __syncthreads();

    const int w = tid >> 5, lane = tid & 31;
    if (w < Hv) {
        float mx = -1e30f;
        for (int n = lane; n < Nv; n += 32) mx = fmaxf(mx, Ls[w][n]);
#pragma unroll
        for (int o = 16; o; o >>= 1) mx = fmaxf(mx, __shfl_xor_sync(0xffffffffu, mx, o));
        float s = 0.f;
        for (int n = lane; n < Nv; n += 32) {
            float e = __expf(Ls[w][n] - mx);
            Ls[w][n] = e;
            s += e;
        }
#pragma unroll
        for (int o = 16; o; o >>= 1) s += __shfl_xor_sync(0xffffffffu, s, o);
        float inv = 1.f / s;
        for (int n = lane; n < Nv; n += 32) Ls[w][n] *= inv;
    }
    __syncthreads();

    float p[Hv];
#pragma unroll
    for (int h = 0; h < Hv; h++) p[h] = Ls[h][tid];
#pragma unroll
    for (int g = 0; g < Hv; g++) {
        float a = bw_s[g];
#pragma unroll
        for (int h = 0; h < Hv; h++) a += ww_s[g * Hv + h] * p[h];
        g_S[(((size_t)b * Hv + g) * Nv + m) * Nv + tid] = a;
    }
}

// Kernel 4: O[bh] = P'[bh] (576x576) @ V[bh] (576x64)  -> g_O (b, m, h*64+d)
// 128x64x8 tile, 128 threads, 8x8 per thread.
__global__ __launch_bounds__(128) void pv_gemm_kernel() {
    __shared__ float As[8][SW];
    __shared__ float Bs[8][68];
    const int bh = blockIdx.y;
    const int m0 = blockIdx.x << 7;
    const float* __restrict__ A = g_S + (size_t)bh * Nv * Nv;   // 576x576
    const float* __restrict__ V = g_v + (size_t)bh * Nv * HDv;  // 576x64
    const int tid = threadIdx.x;
    const int tx = tid & 7, ty = tid >> 3;
    const int rmA = min(m0 + tid, Nv - 1);
    const int br = tid >> 4, bc = (tid & 15) << 2;

    float acc[8][8];
#pragma unroll
    for (int i = 0; i < 8; i++)
#pragma unroll
        for (int j = 0; j < 8; j++) acc[i][j] = 0.f;

    float4 a0Reg = *(const float4*)(A + (size_t)rmA * Nv + 0);
    float4 a1Reg = *(const float4*)(A + (size_t)rmA * Nv + 4);
    float4 bReg  = *(const float4*)(V + (size_t)br * HDv + bc);
    for (int kb = 0; kb < Nv; kb += 8) {
        __syncthreads();
        As[0][tid] = a0Reg.x; As[1][tid] = a0Reg.y; As[2][tid] = a0Reg.z; As[3][tid] = a0Reg.w;
        As[4][tid] = a1Reg.x; As[5][tid] = a1Reg.y; As[6][tid] = a1Reg.z; As[7][tid] = a1Reg.w;
        *(float4*)&Bs[br][bc] = bReg;
        __syncthreads();
        if (kb + 8 < Nv) {
            a0Reg = *(const float4*)(A + (size_t)rmA * Nv + kb + 8);
            a1Reg = *(const float4*)(A + (size_t)rmA * Nv + kb + 12);
            bReg  = *(const float4*)(V + (size_t)(kb + 8 + br) * HDv + bc);
        }
#pragma unroll
        for (int k = 0; k < 8; k++) {
            float4 a0 = *(const float4*)&As[k][ty << 2];
            float4 a1 = *(const float4*)&As[k][64 + (ty << 2)];
            float4 b0 = *(const float4*)&Bs[k][tx << 2];
            float4 b1 = *(const float4*)&Bs[k][32 + (tx << 2)];
            float av[8] = {a0.x, a0.y, a0.z, a0.w, a1.x, a1.y, a1.z, a1.w};
            float bv[8] = {b0.x, b0.y, b0.z, b0.w, b1.x, b1.y, b1.z, b1.w};
#pragma unroll
            for (int i = 0; i < 8; i++)
#pragma unroll
                for (int j = 0; j < 8; j++) acc[i][j] += av[i] * bv[j];
        }
    }

    const int b = bh / Hv, h = bh % Hv;
#pragma unroll
    for (int g = 0; g < 2; g++) {
        const int d = (g << 5) + (tx << 2);
#pragma unroll
        for (int i = 0; i < 8; i++) {
            const int m = m0 + ((i < 4) ? (ty << 2) + i : 64 + (ty << 2) + i - 4);
            if (m >= Nv) continue;
            *(float4*)&g_O[((size_t)b * Nv + m) * Cv + h * HDv + d] =
                make_float4(acc[i][g*4+0], acc[i][g*4+1], acc[i][g*4+2], acc[i][g*4+3]);
        }
    }
}

// Kernel 5: out = O (9216x768) @ Wproj^T + bproj
__global__ __launch_bounds__(256) void proj_gemm_kernel(const float* __restrict__ W,
                                                        const float* __restrict__ bias,
                                                        float* __restrict__ Y) {
    GEMM_CORE_DECL
    const int K = Cv;
    const int m0 = blockIdx.y << 7;
    const int n0 = blockIdx.x << 7;
    const float* __restrict__ X = g_O;

    float4 aReg = *(const float4*)(X + (size_t)(m0 + ar) * K + ac);
    float4 bReg = *(const float4*)(W + (size_t)(n0 + ar) * K + ac);
    for (int kb = 0; kb < K; kb += 8) {
        __syncthreads();
        As[ac + 0][ar] = aReg.x; As[ac + 1][ar] = aReg.y; As[ac + 2][ar] = aReg.z; As[ac + 3][ar] = aReg.w;
        Bs[ac + 0][ar] = bReg.x; Bs[ac + 1][ar] = bReg.y; Bs[ac + 2][ar] = bReg.z; Bs[ac + 3][ar] = bReg.w;
        __syncthreads();
        if (kb + 8 < K) {
            aReg = *(const float4*)(X + (size_t)(m0 + ar) * K + kb + 8 + ac);
            bReg = *(const float4*)(W + (size_t)(n0 + ar) * K + kb + 8 + ac);
        }
        GEMM_COMPUTE_CHUNK
    }

#pragma unroll
    for (int g = 0; g < 2; g++) {
        const int jb = n0 + (g << 6) + (tx << 2);
        float4 bi = *(const float4*)&bias[jb];
#pragma unroll
        for (int i = 0; i < 8; i++) {
            const int r = m0 + ((i < 4) ? (ty << 2) + i : 64 + (ty << 2) + i - 4);
            *(float4*)&Y[(size_t)r * Cv + jb] =
                make_float4(acc[i][g*4+0] + bi.x, acc[i][g*4+1] + bi.y,
                            acc[i][g*4+2] + bi.z, acc[i][g*4+3] + bi.w);
        }
    }
}

extern "C" void kernel_launch(void* const* d_in, const int* in_sizes, int n_in,
                              void* d_out, int out_size) {
    const float* x     = (const float*)d_in[0];
    const float* Wqkv  = (const float*)d_in[1];
    const float* Wl    = (const float*)d_in[2];
    const float* bl    = (const float*)d_in[3];
    const float* Ww    = (const float*)d_in[4];
    const float* bw    = (const float*)d_in[5];
    const float* Wproj = (const float*)d_in[6];
    const float* bproj = (const float*)d_in[7];
    float* out = (float*)d_out;

    // 1) qkv projection -> g_q (scaled), g_k, g_v   (N=2304, M=9216)
    qkv_gemm_kernel<<<dim3(3 * Cv / 128, MROWS / 128), 256>>>(x, Wqkv);
    // 2) scores S = q @ k^T per (b,h)  (576x576, guarded 128-tiles)
    scores_gemm_kernel<<<dim3(5, 5, BH), 256>>>();
    // 3) head-mix -> softmax -> head-mix (in place on g_S)
    mix_softmax_kernel<<<dim3(Nv, Bv), Nv>>>(Wl, bl, Ww, bw);
    // 4) O = P' @ V  -> (B,N,C) layout
    pv_gemm_kernel<<<dim3(5, BH), 128>>>();
    // 5) output projection + bias   (N=768, M=9216)
    proj_gemm_kernel<<<dim3(Cv / 128, MROWS / 128), 256>>>(Wproj, bproj, out);
}

// round 6
// speedup vs baseline: 2.0268x; 1.5232x over previous
#include <cuda_runtime.h>
#include <cstdint>

// Problem constants
#define Bv 16
#define Nv 576
#define Cv 768
#define Hv 12
#define HDv 64
#define BH (Bv*Hv)            // 192
#define MROWS (Bv*Nv)         // 9216

// Scratch (device globals; no allocation allowed)
__device__ float g_q[BH * Nv * HDv];     // (b,h,n,d), pre-scaled by 0.125
__device__ float g_k[BH * Nv * HDv];
__device__ float g_v[BH * Nv * HDv];
__device__ float g_S[(size_t)BH * Nv * Nv];      // scores / mixed probs, (b,h,m,n)
__device__ float g_O[MROWS * Cv];                // (b,n, h*64+d)

// ---------------------------------------------------------------------------
// tf32 warp MMA helpers
// ---------------------------------------------------------------------------
__device__ __forceinline__ uint32_t f2tf(float f) {
    uint32_t u;
    asm("cvt.rna.tf32.f32 %0, %1;" : "=r"(u) : "f"(f));
    return u;
}

__device__ __forceinline__ void mma_tf32(float* c, const uint32_t* a, const uint32_t* b) {
    asm volatile(
        "mma.sync.aligned.m16n8k8.row.col.f32.tf32.tf32.f32 "
        "{%0,%1,%2,%3}, {%4,%5,%6,%7}, {%8,%9}, {%0,%1,%2,%3};\n"
        : "+f"(c[0]), "+f"(c[1]), "+f"(c[2]), "+f"(c[3])
        : "r"(a[0]), "r"(a[1]), "r"(a[2]), "r"(a[3]), "r"(b[0]), "r"(b[1]));
}

#define PAD 36   // smem row stride in words: bank permutation; 144B keeps 16B alignment

// ---------------------------------------------------------------------------
// Kernel 1: qkv = x @ Wqkv^T  (M=9216, N=2304, K=768), scatter to g_q/g_k/g_v
// 128x128x32 tile, 256 threads, warp grid 2x4, warp tile 64x32.
// ---------------------------------------------------------------------------
__global__ __launch_bounds__(256) void qkv_gemm_kernel(const float* __restrict__ X,
                                                       const float* __restrict__ W) {
    __shared__ uint32_t As[128][PAD];
    __shared__ uint32_t Bs[128][PAD];
    const int tid = threadIdx.x;
    const int wid = tid >> 5, lane = tid & 31;
    const int wm = (wid >> 2) << 6;        // 0 / 64
    const int wn = (wid & 3) << 5;         // 0..96
    const int g = lane >> 2, t = lane & 3;
    const int m0 = blockIdx.y << 7, n0 = blockIdx.x << 7;
    const int lr = tid >> 3, lc = (tid & 7) << 2;
    const int K = Cv;

    float acc[4][4][4];
#pragma unroll
    for (int im = 0; im < 4; im++)
#pragma unroll
        for (int jn = 0; jn < 4; jn++)
#pragma unroll
            for (int r = 0; r < 4; r++) acc[im][jn][r] = 0.f;

    for (int kb = 0; kb < K; kb += 32) {
        __syncthreads();
#pragma unroll
        for (int i = 0; i < 4; i++) {
            float4 va = *(const float4*)(X + (size_t)(m0 + lr + 32 * i) * K + kb + lc);
            float4 vb = *(const float4*)(W + (size_t)(n0 + lr + 32 * i) * K + kb + lc);
            *(uint4*)&As[lr + 32 * i][lc] = make_uint4(f2tf(va.x), f2tf(va.y), f2tf(va.z), f2tf(va.w));
            *(uint4*)&Bs[lr + 32 * i][lc] = make_uint4(f2tf(vb.x), f2tf(vb.y), f2tf(vb.z), f2tf(vb.w));
        }
        __syncthreads();
#pragma unroll
        for (int k8 = 0; k8 < 32; k8 += 8) {
            uint32_t a[4][4], b[4][2];
#pragma unroll
            for (int im = 0; im < 4; im++) {
                int r0 = wm + (im << 4) + g;
                a[im][0] = As[r0][k8 + t];     a[im][1] = As[r0 + 8][k8 + t];
                a[im][2] = As[r0][k8 + t + 4]; a[im][3] = As[r0 + 8][k8 + t + 4];
            }
#pragma unroll
            for (int jn = 0; jn < 4; jn++) {
                int c0 = wn + (jn << 3) + g;
                b[jn][0] = Bs[c0][k8 + t];
                b[jn][1] = Bs[c0][k8 + t + 4];
            }
#pragma unroll
            for (int im = 0; im < 4; im++)
#pragma unroll
                for (int jn = 0; jn < 4; jn++) mma_tf32(acc[im][jn], a[im], b[jn]);
        }
    }

    // epilogue: scatter to g_q/g_k/g_v
#pragma unroll
    for (int jn = 0; jn < 4; jn++) {
        const int col = n0 + wn + (jn << 3) + (t << 1);
        const int tsel = col / Cv;
        const int rem = col % Cv;
        const int h = rem >> 6, d = rem & 63;
        float* dst = (tsel == 0) ? g_q : (tsel == 1) ? g_k : g_v;
        const float scale = (tsel == 0) ? 0.125f : 1.0f;
#pragma unroll
        for (int im = 0; im < 4; im++) {
            int r = m0 + wm + (im << 4) + g;
            {
                int bb = r / Nv, n = r % Nv;
                *(float2*)&dst[(((size_t)bb * Hv + h) * Nv + n) * HDv + d] =
                    make_float2(acc[im][jn][0] * scale, acc[im][jn][1] * scale);
            }
            int r2 = r + 8;
            {
                int bb = r2 / Nv, n = r2 % Nv;
                *(float2*)&dst[(((size_t)bb * Hv + h) * Nv + n) * HDv + d] =
                    make_float2(acc[im][jn][2] * scale, acc[im][jn][3] * scale);
            }
        }
    }
}

// ---------------------------------------------------------------------------
// Kernel 2: S[bh] = q[bh] (576x64) @ k[bh]^T   (guarded 128x128 tiles, K=64)
// ---------------------------------------------------------------------------
__global__ __launch_bounds__(256) void scores_gemm_kernel() {
    __shared__ uint32_t As[128][PAD];
    __shared__ uint32_t Bs[128][PAD];
    const int tid = threadIdx.x;
    const int wid = tid >> 5, lane = tid & 31;
    const int wm = (wid >> 2) << 6;
    const int wn = (wid & 3) << 5;
    const int g = lane >> 2, t = lane & 3;
    const int bh = blockIdx.z;
    const int m0 = blockIdx.x << 7, n0 = blockIdx.y << 7;
    const int lr = tid >> 3, lc = (tid & 7) << 2;
    const float* __restrict__ X = g_q + (size_t)bh * Nv * HDv;
    const float* __restrict__ W = g_k + (size_t)bh * Nv * HDv;

    float acc[4][4][4];
#pragma unroll
    for (int im = 0; im < 4; im++)
#pragma unroll
        for (int jn = 0; jn < 4; jn++)
#pragma unroll
            for (int r = 0; r < 4; r++) acc[im][jn][r] = 0.f;

#pragma unroll
    for (int kb = 0; kb < HDv; kb += 32) {
        __syncthreads();
#pragma unroll
        for (int i = 0; i < 4; i++) {
            int rA = min(m0 + lr + 32 * i, Nv - 1);
            int rB = min(n0 + lr + 32 * i, Nv - 1);
            float4 va = *(const float4*)(X + (size_t)rA * HDv + kb + lc);
            float4 vb = *(const float4*)(W + (size_t)rB * HDv + kb + lc);
            *(uint4*)&As[lr + 32 * i][lc] = make_uint4(f2tf(va.x), f2tf(va.y), f2tf(va.z), f2tf(va.w));
            *(uint4*)&Bs[lr + 32 * i][lc] = make_uint4(f2tf(vb.x), f2tf(vb.y), f2tf(vb.z), f2tf(vb.w));
        }
        __syncthreads();
#pragma unroll
        for (int k8 = 0; k8 < 32; k8 += 8) {
            uint32_t a[4][4], b[4][2];
#pragma unroll
            for (int im = 0; im < 4; im++) {
                int r0 = wm + (im << 4) + g;
                a[im][0] = As[r0][k8 + t];     a[im][1] = As[r0 + 8][k8 + t];
                a[im][2] = As[r0][k8 + t + 4]; a[im][3] = As[r0 + 8][k8 + t + 4];
            }
#pragma unroll
            for (int jn = 0; jn < 4; jn++) {
                int c0 = wn + (jn << 3) + g;
                b[jn][0] = Bs[c0][k8 + t];
                b[jn][1] = Bs[c0][k8 + t + 4];
            }
#pragma unroll
            for (int im = 0; im < 4; im++)
#pragma unroll
                for (int jn = 0; jn < 4; jn++) mma_tf32(acc[im][jn], a[im], b[jn]);
        }
    }

    float* Sp = g_S + (size_t)bh * Nv * Nv;
#pragma unroll
    for (int jn = 0; jn < 4; jn++) {
        const int col = n0 + wn + (jn << 3) + (t << 1);
        if (col >= Nv) continue;
#pragma unroll
        for (int im = 0; im < 4; im++) {
            int r = m0 + wm + (im << 4) + g;
            if (r < Nv)
                *(float2*)&Sp[(size_t)r * Nv + col] = make_float2(acc[im][jn][0], acc[im][jn][1]);
            if (r + 8 < Nv)
                *(float2*)&Sp[(size_t)(r + 8) * Nv + col] = make_float2(acc[im][jn][2], acc[im][jn][3]);
        }
    }
}

// ---------------------------------------------------------------------------
// Kernel 3: per (b,m): pre-mix (Wl,bl) -> softmax -> post-mix (Ww,bw), in place
// ---------------------------------------------------------------------------
__global__ __launch_bounds__(576) void mix_softmax_kernel(const float* __restrict__ Wl,
                                                          const float* __restrict__ bl,
                                                          const float* __restrict__ Ww,
                                                          const float* __restrict__ bw) {
    __shared__ float Ls[Hv][Nv];
    __shared__ float wl_s[Hv * Hv], ww_s[Hv * Hv], bl_s[Hv], bw_s[Hv];
    const int m = blockIdx.x;
    const int b = blockIdx.y;
    const int tid = threadIdx.x;

    if (tid < Hv * Hv) { wl_s[tid] = Wl[tid]; ww_s[tid] = Ww[tid]; }
    if (tid < Hv) { bl_s[tid] = bl[tid]; bw_s[tid] = bw[tid]; }
    __syncthreads();

    float L[Hv];
#pragma unroll
    for (int g = 0; g < Hv; g++) L[g] = bl_s[g];
#pragma unroll
    for (int h = 0; h < Hv; h++) {
        float sval = g_S[(((size_t)b * Hv + h) * Nv + m) * Nv + tid];
#pragma unroll
        for (int g = 0; g < Hv; g++) L[g] += wl_s[g * Hv + h] * sval;
    }
#pragma unroll
    for (int g = 0; g < Hv; g++) Ls[g][tid] = L[g];
    __syncthreads();

    const int w = tid >> 5, lane = tid & 31;
    if (w < Hv) {
        float mx = -1e30f;
        for (int n = lane; n < Nv; n += 32) mx = fmaxf(mx, Ls[w][n]);
#pragma unroll
        for (int o = 16; o; o >>= 1) mx = fmaxf(mx, __shfl_xor_sync(0xffffffffu, mx, o));
        float s = 0.f;
        for (int n = lane; n < Nv; n += 32) {
            float e = __expf(Ls[w][n] - mx);
            Ls[w][n] = e;
            s += e;
        }
#pragma unroll
        for (int o = 16; o; o >>= 1) s += __shfl_xor_sync(0xffffffffu, s, o);
        float inv = 1.f / s;
        for (int n = lane; n < Nv; n += 32) Ls[w][n] *= inv;
    }
    __syncthreads();

    float p[Hv];
#pragma unroll
    for (int h = 0; h < Hv; h++) p[h] = Ls[h][tid];
#pragma unroll
    for (int g = 0; g < Hv; g++) {
        float a = bw_s[g];
#pragma unroll
        for (int h = 0; h < Hv; h++) a += ww_s[g * Hv + h] * p[h];
        g_S[(((size_t)b * Hv + g) * Nv + m) * Nv + tid] = a;
    }
}

// ---------------------------------------------------------------------------
// Kernel 4: O[bh] = P'[bh] (576x576) @ V[bh] (576x64) -> g_O (b,m,h*64+d)
// 128x64x32 tile, 256 threads, warp grid 4x2, warp tile 32x32.
// ---------------------------------------------------------------------------
__global__ __launch_bounds__(256) void pv_gemm_kernel() {
    __shared__ uint32_t As[128][PAD];
    __shared__ uint32_t Bs[64][PAD];
    const int tid = threadIdx.x;
    const int wid = tid >> 5, lane = tid & 31;
    const int wm = (wid >> 1) << 5;        // 0,32,64,96
    const int wn = (wid & 1) << 5;         // 0,32
    const int g = lane >> 2, t = lane & 3;
    const int bh = blockIdx.x;
    const int m0 = blockIdx.y << 7;
    const int lr = tid >> 3, lc = (tid & 7) << 2;
    const int vr = tid >> 4, vc = (tid & 15) << 2;
    const float* __restrict__ A = g_S + (size_t)bh * Nv * Nv;
    const float* __restrict__ V = g_v + (size_t)bh * Nv * HDv;

    float acc[2][4][4];
#pragma unroll
    for (int im = 0; im < 2; im++)
#pragma unroll
        for (int jn = 0; jn < 4; jn++)
#pragma unroll
            for (int r = 0; r < 4; r++) acc[im][jn][r] = 0.f;

    for (int kb = 0; kb < Nv; kb += 32) {
        __syncthreads();
#pragma unroll
        for (int i = 0; i < 4; i++) {
            int rA = min(m0 + lr + 32 * i, Nv - 1);
            float4 va = *(const float4*)(A + (size_t)rA * Nv + kb + lc);
            *(uint4*)&As[lr + 32 * i][lc] = make_uint4(f2tf(va.x), f2tf(va.y), f2tf(va.z), f2tf(va.w));
        }
#pragma unroll
        for (int i = 0; i < 2; i++) {
            float4 vv = *(const float4*)(V + (size_t)(kb + vr + 16 * i) * HDv + vc);
            Bs[vc + 0][vr + 16 * i] = f2tf(vv.x);
            Bs[vc + 1][vr + 16 * i] = f2tf(vv.y);
            Bs[vc + 2][vr + 16 * i] = f2tf(vv.z);
            Bs[vc + 3][vr + 16 * i] = f2tf(vv.w);
        }
        __syncthreads();
#pragma unroll
        for (int k8 = 0; k8 < 32; k8 += 8) {
            uint32_t a[2][4], b[4][2];
#pragma unroll
            for (int im = 0; im < 2; im++) {
                int r0 = wm + (im << 4) + g;
                a[im][0] = As[r0][k8 + t];     a[im][1] = As[r0 + 8][k8 + t];
                a[im][2] = As[r0][k8 + t + 4]; a[im][3] = As[r0 + 8][k8 + t + 4];
            }
#pragma unroll
            for (int jn = 0; jn < 4; jn++) {
                int c0 = wn + (jn << 3) + g;
                b[jn][0] = Bs[c0][k8 + t];
                b[jn][1] = Bs[c0][k8 + t + 4];
            }
#pragma unroll
            for (int im = 0; im < 2; im++)
#pragma unroll
                for (int jn = 0; jn < 4; jn++) mma_tf32(acc[im][jn], a[im], b[jn]);
        }
    }

    const int bb = bh / Hv, h = bh % Hv;
#pragma unroll
    for (int jn = 0; jn < 4; jn++) {
        const int d = wn + (jn << 3) + (t << 1);
#pragma unroll
        for (int im = 0; im < 2; im++) {
            int m = m0 + wm + (im << 4) + g;
            if (m < Nv)
                *(float2*)&g_O[((size_t)bb * Nv + m) * Cv + h * HDv + d] =
                    make_float2(acc[im][jn][0], acc[im][jn][1]);
            if (m + 8 < Nv)
                *(float2*)&g_O[((size_t)bb * Nv + m + 8) * Cv + h * HDv + d] =
                    make_float2(acc[im][jn][2], acc[im][jn][3]);
        }
    }
}

// ---------------------------------------------------------------------------
// Kernel 5: out = O (9216x768) @ Wproj^T + bproj
// ---------------------------------------------------------------------------
__global__ __launch_bounds__(256) void proj_gemm_kernel(const float* __restrict__ W,
                                                        const float* __restrict__ bias,
                                                        float* __restrict__ Y) {
    __shared__ uint32_t As[128][PAD];
    __shared__ uint32_t Bs[128][PAD];
    const int tid = threadIdx.x;
    const int wid = tid >> 5, lane = tid & 31;
    const int wm = (wid >> 2) << 6;
    const int wn = (wid & 3) << 5;
    const int g = lane >> 2, t = lane & 3;
    const int m0 = blockIdx.y << 7, n0 = blockIdx.x << 7;
    const int lr = tid >> 3, lc = (tid & 7) << 2;
    const int K = Cv;
    const float* __restrict__ X = g_O;

    float acc[4][4][4];
#pragma unroll
    for (int im = 0; im < 4; im++)
#pragma unroll
        for (int jn = 0; jn < 4; jn++)
#pragma unroll
            for (int r = 0; r < 4; r++) acc[im][jn][r] = 0.f;

    for (int kb = 0; kb < K; kb += 32) {
        __syncthreads();
#pragma unroll
        for (int i = 0; i < 4; i++) {
            float4 va = *(const float4*)(X + (size_t)(m0 + lr + 32 * i) * K + kb + lc);
            float4 vb = *(const float4*)(W + (size_t)(n0 + lr + 32 * i) * K + kb + lc);
            *(uint4*)&As[lr + 32 * i][lc] = make_uint4(f2tf(va.x), f2tf(va.y), f2tf(va.z), f2tf(va.w));
            *(uint4*)&Bs[lr + 32 * i][lc] = make_uint4(f2tf(vb.x), f2tf(vb.y), f2tf(vb.z), f2tf(vb.w));
        }
        __syncthreads();
#pragma unroll
        for (int k8 = 0; k8 < 32; k8 += 8) {
            uint32_t a[4][4], b[4][2];
#pragma unroll
            for (int im = 0; im < 4; im++) {
                int r0 = wm + (im << 4) + g;
                a[im][0] = As[r0][k8 + t];     a[im][1] = As[r0 + 8][k8 + t];
                a[im][2] = As[r0][k8 + t + 4]; a[im][3] = As[r0 + 8][k8 + t + 4];
            }
#pragma unroll
            for (int jn = 0; jn < 4; jn++) {
                int c0 = wn + (jn << 3) + g;
                b[jn][0] = Bs[c0][k8 + t];
                b[jn][1] = Bs[c0][k8 + t + 4];
            }
#pragma unroll
            for (int im = 0; im < 4; im++)
#pragma unroll
                for (int jn = 0; jn < 4; jn++) mma_tf32(acc[im][jn], a[im], b[jn]);
        }
    }

#pragma unroll
    for (int jn = 0; jn < 4; jn++) {
        const int col = n0 + wn + (jn << 3) + (t << 1);
        const float2 bi = *(const float2*)&bias[col];
#pragma unroll
        for (int im = 0; im < 4; im++) {
            int r = m0 + wm + (im << 4) + g;
            *(float2*)&Y[(size_t)r * Cv + col] =
                make_float2(acc[im][jn][0] + bi.x, acc[im][jn][1] + bi.y);
            *(float2*)&Y[(size_t)(r + 8) * Cv + col] =
                make_float2(acc[im][jn][2] + bi.x, acc[im][jn][3] + bi.y);
        }
    }
}

extern "C" void kernel_launch(void* const* d_in, const int* in_sizes, int n_in,
                              void* d_out, int out_size) {
    const float* x     = (const float*)d_in[0];
    const float* Wqkv  = (const float*)d_in[1];
    const float* Wl    = (const float*)d_in[2];
    const float* bl    = (const float*)d_in[3];
    const float* Ww    = (const float*)d_in[4];
    const float* bw    = (const float*)d_in[5];
    const float* Wproj = (const float*)d_in[6];
    const float* bproj = (const float*)d_in[7];
    float* out = (float*)d_out;

    qkv_gemm_kernel<<<dim3(3 * Cv / 128, MROWS / 128), 256>>>(x, Wqkv);
    scores_gemm_kernel<<<dim3(5, 5, BH), 256>>>();
    mix_softmax_kernel<<<dim3(Nv, Bv), Nv>>>(Wl, bl, Ww, bw);
    pv_gemm_kernel<<<dim3(BH, 5), 256>>>();
    proj_gemm_kernel<<<dim3(Cv / 128, MROWS / 128), 256>>>(Wproj, bproj, out);
}

// round 8
// speedup vs baseline: 2.3681x; 1.1684x over previous
#include <cuda_runtime.h>
#include <cstdint>

// Problem constants
#define Bv 16
#define Nv 576
#define Cv 768
#define Hv 12
#define HDv 64
#define BH (Bv*Hv)            // 192
#define MROWS (Bv*Nv)         // 9216

// Scratch (device globals). All values stored PRE-ROUNDED to tf32 (RNA) by
// their producer; consumers load raw bits straight into the MMA path.
__device__ float g_q[BH * Nv * HDv];     // (b,h,n,d), pre-scaled by 0.125
__device__ float g_k[BH * Nv * HDv];
__device__ float g_v[BH * Nv * HDv];
__device__ float g_S[(size_t)BH * Nv * Nv];      // scores -> mixed probs, (b,h,m,n)
__device__ float g_O[MROWS * Cv];                // (b,n, h*64+d)

__device__ __forceinline__ uint32_t f2tf(float f) {
    uint32_t u;
    asm("cvt.rna.tf32.f32 %0, %1;" : "=r"(u) : "f"(f));
    return u;
}
__device__ __forceinline__ float f2tf_f(float f) { return __uint_as_float(f2tf(f)); }

__device__ __forceinline__ void mma_tf32(float* c, const uint32_t* a, const uint32_t* b) {
    asm volatile(
        "mma.sync.aligned.m16n8k8.row.col.f32.tf32.tf32.f32 "
        "{%0,%1,%2,%3}, {%4,%5,%6,%7}, {%8,%9}, {%0,%1,%2,%3};\n"
        : "+f"(c[0]), "+f"(c[1]), "+f"(c[2]), "+f"(c[3])
        : "r"(a[0]), "r"(a[1]), "r"(a[2]), "r"(a[3]), "r"(b[0]), "r"(b[1]));
}

#define PAD 36    // [row][k] operand stride: fragment reads map to 4g+t -> conflict-free
#define PADB 72   // [k][n] operand stride (64 data + 8 pad): reads map to 8t+g -> conflict-free

// ---------------------------------------------------------------------------
// Kernel 1: qkv = x @ Wqkv^T  (M=9216, N=2304, K=768) -> g_q(*0.125)/g_k/g_v
// 128x128x32 tile, 256 threads, warp grid 2x4, warp tile 64x32. cvt at fill.
// ---------------------------------------------------------------------------
__global__ __launch_bounds__(256) void qkv_gemm_kernel(const float* __restrict__ X,
                                                       const float* __restrict__ W) {
    __shared__ uint32_t As[128][PAD];
    __shared__ uint32_t Bs[128][PAD];
    const int tid = threadIdx.x;
    const int wid = tid >> 5, lane = tid & 31;
    const int wm = (wid >> 2) << 6;
    const int wn = (wid & 3) << 5;
    const int g = lane >> 2, t = lane & 3;
    const int m0 = blockIdx.y << 7, n0 = blockIdx.x << 7;
    const int lr = tid >> 3, lc = (tid & 7) << 2;
    const int K = Cv;

    float acc[4][4][4];
#pragma unroll
    for (int im = 0; im < 4; im++)
#pragma unroll
        for (int jn = 0; jn < 4; jn++)
#pragma unroll
            for (int r = 0; r < 4; r++) acc[im][jn][r] = 0.f;

    float4 pa[4], pb[4];
#pragma unroll
    for (int i = 0; i < 4; i++) {
        pa[i] = *(const float4*)(X + (size_t)(m0 + lr + 32 * i) * K + lc);
        pb[i] = *(const float4*)(W + (size_t)(n0 + lr + 32 * i) * K + lc);
    }

    for (int kb = 0; kb < K; kb += 32) {
        __syncthreads();
#pragma unroll
        for (int i = 0; i < 4; i++) {
            *(uint4*)&As[lr + 32 * i][lc] = make_uint4(f2tf(pa[i].x), f2tf(pa[i].y), f2tf(pa[i].z), f2tf(pa[i].w));
            *(uint4*)&Bs[lr + 32 * i][lc] = make_uint4(f2tf(pb[i].x), f2tf(pb[i].y), f2tf(pb[i].z), f2tf(pb[i].w));
        }
        __syncthreads();
        if (kb + 32 < K) {
#pragma unroll
            for (int i = 0; i < 4; i++) {
                pa[i] = *(const float4*)(X + (size_t)(m0 + lr + 32 * i) * K + kb + 32 + lc);
                pb[i] = *(const float4*)(W + (size_t)(n0 + lr + 32 * i) * K + kb + 32 + lc);
            }
        }
#pragma unroll
        for (int k8 = 0; k8 < 32; k8 += 8) {
            uint32_t a[4][4], b[4][2];
#pragma unroll
            for (int im = 0; im < 4; im++) {
                int r0 = wm + (im << 4) + g;
                a[im][0] = As[r0][k8 + t];     a[im][1] = As[r0 + 8][k8 + t];
                a[im][2] = As[r0][k8 + t + 4]; a[im][3] = As[r0 + 8][k8 + t + 4];
            }
#pragma unroll
            for (int jn = 0; jn < 4; jn++) {
                int c0 = wn + (jn << 3) + g;
                b[jn][0] = Bs[c0][k8 + t];
                b[jn][1] = Bs[c0][k8 + t + 4];
            }
#pragma unroll
            for (int im = 0; im < 4; im++)
#pragma unroll
                for (int jn = 0; jn < 4; jn++) mma_tf32(acc[im][jn], a[im], b[jn]);
        }
    }

    // epilogue: tf32-round + scatter
#pragma unroll
    for (int jn = 0; jn < 4; jn++) {
        const int col = n0 + wn + (jn << 3) + (t << 1);
        const int tsel = col / Cv;
        const int rem = col % Cv;
        const int h = rem >> 6, d = rem & 63;
        float* dst = (tsel == 0) ? g_q : (tsel == 1) ? g_k : g_v;
        const float scale = (tsel == 0) ? 0.125f : 1.0f;
#pragma unroll
        for (int im = 0; im < 4; im++) {
            int r = m0 + wm + (im << 4) + g;
            {
                int bb = r / Nv, n = r % Nv;
                *(float2*)&dst[(((size_t)bb * Hv + h) * Nv + n) * HDv + d] =
                    make_float2(f2tf_f(acc[im][jn][0] * scale), f2tf_f(acc[im][jn][1] * scale));
            }
            int r2 = r + 8;
            {
                int bb = r2 / Nv, n = r2 % Nv;
                *(float2*)&dst[(((size_t)bb * Hv + h) * Nv + n) * HDv + d] =
                    make_float2(f2tf_f(acc[im][jn][2] * scale), f2tf_f(acc[im][jn][3] * scale));
            }
        }
    }
}

// ---------------------------------------------------------------------------
// Kernel 2: S[bh] = q[bh] (576x64) @ k[bh]^T  (guarded 128x128 tiles, K=64)
// inputs pre-rounded: raw loads, no cvt.
// ---------------------------------------------------------------------------
__global__ __launch_bounds__(256) void scores_gemm_kernel() {
    __shared__ uint32_t As[128][PAD];
    __shared__ uint32_t Bs[128][PAD];
    const int tid = threadIdx.x;
    const int wid = tid >> 5, lane = tid & 31;
    const int wm = (wid >> 2) << 6;
    const int wn = (wid & 3) << 5;
    const int g = lane >> 2, t = lane & 3;
    const int bh = blockIdx.z;
    const int m0 = blockIdx.x << 7, n0 = blockIdx.y << 7;
    const int lr = tid >> 3, lc = (tid & 7) << 2;
    const float* __restrict__ X = g_q + (size_t)bh * Nv * HDv;
    const float* __restrict__ W = g_k + (size_t)bh * Nv * HDv;

    float acc[4][4][4];
#pragma unroll
    for (int im = 0; im < 4; im++)
#pragma unroll
        for (int jn = 0; jn < 4; jn++)
#pragma unroll
            for (int r = 0; r < 4; r++) acc[im][jn][r] = 0.f;

    int rA[4], rB[4];
#pragma unroll
    for (int i = 0; i < 4; i++) {
        rA[i] = min(m0 + lr + 32 * i, Nv - 1);
        rB[i] = min(n0 + lr + 32 * i, Nv - 1);
    }
    uint4 pa[4], pb[4];
#pragma unroll
    for (int i = 0; i < 4; i++) {
        pa[i] = *(const uint4*)(X + (size_t)rA[i] * HDv + lc);
        pb[i] = *(const uint4*)(W + (size_t)rB[i] * HDv + lc);
    }

#pragma unroll
    for (int kb = 0; kb < HDv; kb += 32) {
        __syncthreads();
#pragma unroll
        for (int i = 0; i < 4; i++) {
            *(uint4*)&As[lr + 32 * i][lc] = pa[i];
            *(uint4*)&Bs[lr + 32 * i][lc] = pb[i];
        }
        __syncthreads();
        if (kb + 32 < HDv) {
#pragma unroll
            for (int i = 0; i < 4; i++) {
                pa[i] = *(const uint4*)(X + (size_t)rA[i] * HDv + kb + 32 + lc);
                pb[i] = *(const uint4*)(W + (size_t)rB[i] * HDv + kb + 32 + lc);
            }
        }
#pragma unroll
        for (int k8 = 0; k8 < 32; k8 += 8) {
            uint32_t a[4][4], b[4][2];
#pragma unroll
            for (int im = 0; im < 4; im++) {
                int r0 = wm + (im << 4) + g;
                a[im][0] = As[r0][k8 + t];     a[im][1] = As[r0 + 8][k8 + t];
                a[im][2] = As[r0][k8 + t + 4]; a[im][3] = As[r0 + 8][k8 + t + 4];
            }
#pragma unroll
            for (int jn = 0; jn < 4; jn++) {
                int c0 = wn + (jn << 3) + g;
                b[jn][0] = Bs[c0][k8 + t];
                b[jn][1] = Bs[c0][k8 + t + 4];
            }
#pragma unroll
            for (int im = 0; im < 4; im++)
#pragma unroll
                for (int jn = 0; jn < 4; jn++) mma_tf32(acc[im][jn], a[im], b[jn]);
        }
    }

    float* Sp = g_S + (size_t)bh * Nv * Nv;
#pragma unroll
    for (int jn = 0; jn < 4; jn++) {
        const int col = n0 + wn + (jn << 3) + (t << 1);
        if (col >= Nv) continue;
#pragma unroll
        for (int im = 0; im < 4; im++) {
            int r = m0 + wm + (im << 4) + g;
            if (r < Nv)
                *(float2*)&Sp[(size_t)r * Nv + col] =
                    make_float2(f2tf_f(acc[im][jn][0]), f2tf_f(acc[im][jn][1]));
            if (r + 8 < Nv)
                *(float2*)&Sp[(size_t)(r + 8) * Nv + col] =
                    make_float2(f2tf_f(acc[im][jn][2]), f2tf_f(acc[im][jn][3]));
        }
    }
}

// ---------------------------------------------------------------------------
// Kernel 3: per (b,m): pre-mix -> softmax -> post-mix, in place (round on store)
// ---------------------------------------------------------------------------
__global__ __launch_bounds__(576) void mix_softmax_kernel(const float* __restrict__ Wl,
                                                          const float* __restrict__ bl,
                                                          const float* __restrict__ Ww,
                                                          const float* __restrict__ bw) {
    __shared__ float Ls[Hv][Nv];
    __shared__ float wl_s[Hv * Hv], ww_s[Hv * Hv], bl_s[Hv], bw_s[Hv];
    const int m = blockIdx.x;
    const int b = blockIdx.y;
    const int tid = threadIdx.x;

    if (tid < Hv * Hv) { wl_s[tid] = Wl[tid]; ww_s[tid] = Ww[tid]; }
    if (tid < Hv) { bl_s[tid] = bl[tid]; bw_s[tid] = bw[tid]; }
    __syncthreads();

    float L[Hv];
#pragma unroll
    for (int g = 0; g < Hv; g++) L[g] = bl_s[g];
#pragma unroll
    for (int h = 0; h < Hv; h++) {
        float sval = g_S[(((size_t)b * Hv + h) * Nv + m) * Nv + tid];
#pragma unroll
        for (int g = 0; g < Hv; g++) L[g] += wl_s[g * Hv + h] * sval;
    }
#pragma unroll
    for (int g = 0; g < Hv; g++) Ls[g][tid] = L[g];
    __syncthreads();

    const int w = tid >> 5, lane = tid & 31;
    if (w < Hv) {
        float mx = -1e30f;
        for (int n = lane; n < Nv; n += 32) mx = fmaxf(mx, Ls[w][n]);
#pragma unroll
        for (int o = 16; o; o >>= 1) mx = fmaxf(mx, __shfl_xor_sync(0xffffffffu, mx, o));
        float s = 0.f;
        for (int n = lane; n < Nv; n += 32) {
            float e = __expf(Ls[w][n] - mx);
            Ls[w][n] = e;
            s += e;
        }
#pragma unroll
        for (int o = 16; o; o >>= 1) s += __shfl_xor_sync(0xffffffffu, s, o);
        float inv = 1.f / s;
        for (int n = lane; n < Nv; n += 32) Ls[w][n] *= inv;
    }
    __syncthreads();

    float p[Hv];
#pragma unroll
    for (int h = 0; h < Hv; h++) p[h] = Ls[h][tid];
#pragma unroll
    for (int g = 0; g < Hv; g++) {
        float a = bw_s[g];
#pragma unroll
        for (int h = 0; h < Hv; h++) a += ww_s[g * Hv + h] * p[h];
        g_S[(((size_t)b * Hv + g) * Nv + m) * Nv + tid] = f2tf_f(a);
    }
}

// ---------------------------------------------------------------------------
// Kernel 4: O[bh] = P'[bh] (576x576) @ V[bh] (576x64) -> g_O (rounded)
// 128x64x32 tile, 128 threads, warp grid 2x2, warp tile 64x32.
// V kept row-major [k][PADB] -> vectorized fill + conflict-free frag reads.
// ---------------------------------------------------------------------------
__global__ __launch_bounds__(128) void pv_gemm_kernel() {
    __shared__ uint32_t As[128][PAD];
    __shared__ uint32_t Bs[32][PADB];
    const int tid = threadIdx.x;
    const int wid = tid >> 5, lane = tid & 31;
    const int wm = (wid >> 1) << 6;        // 0 / 64
    const int wn = (wid & 1) << 5;         // 0 / 32
    const int g = lane >> 2, t = lane & 3;
    const int bh = blockIdx.x;
    const int m0 = blockIdx.y << 7;
    const int lr = tid >> 3, lc = (tid & 7) << 2;   // A fill: 16 rows/pass, 32 cols
    const int vr = tid >> 4, vc = (tid & 15) << 2;  // V fill: 8 rows/pass, 64 cols
    const float* __restrict__ A = g_S + (size_t)bh * Nv * Nv;
    const float* __restrict__ V = g_v + (size_t)bh * Nv * HDv;

    int rA[8];
#pragma unroll
    for (int i = 0; i < 8; i++) rA[i] = min(m0 + lr + 16 * i, Nv - 1);

    float acc[4][4][4];
#pragma unroll
    for (int im = 0; im < 4; im++)
#pragma unroll
        for (int jn = 0; jn < 4; jn++)
#pragma unroll
            for (int r = 0; r < 4; r++) acc[im][jn][r] = 0.f;

    uint4 pa[8], pvv[4];
#pragma unroll
    for (int i = 0; i < 8; i++) pa[i] = *(const uint4*)(A + (size_t)rA[i] * Nv + lc);
#pragma unroll
    for (int i = 0; i < 4; i++) pvv[i] = *(const uint4*)(V + (size_t)(vr + 8 * i) * HDv + vc);

    for (int kb = 0; kb < Nv; kb += 32) {
        __syncthreads();
#pragma unroll
        for (int i = 0; i < 8; i++) *(uint4*)&As[lr + 16 * i][lc] = pa[i];
#pragma unroll
        for (int i = 0; i < 4; i++) *(uint4*)&Bs[vr + 8 * i][vc] = pvv[i];
        __syncthreads();
        if (kb + 32 < Nv) {
#pragma unroll
            for (int i = 0; i < 8; i++) pa[i] = *(const uint4*)(A + (size_t)rA[i] * Nv + kb + 32 + lc);
#pragma unroll
            for (int i = 0; i < 4; i++) pvv[i] = *(const uint4*)(V + (size_t)(kb + 32 + vr + 8 * i) * HDv + vc);
        }
#pragma unroll
        for (int k8 = 0; k8 < 32; k8 += 8) {
            uint32_t a[4][4], b[4][2];
#pragma unroll
            for (int im = 0; im < 4; im++) {
                int r0 = wm + (im << 4) + g;
                a[im][0] = As[r0][k8 + t];     a[im][1] = As[r0 + 8][k8 + t];
                a[im][2] = As[r0][k8 + t + 4]; a[im][3] = As[r0 + 8][k8 + t + 4];
            }
#pragma unroll
            for (int jn = 0; jn < 4; jn++) {
                int c0 = wn + (jn << 3) + g;
                b[jn][0] = Bs[k8 + t][c0];
                b[jn][1] = Bs[k8 + t + 4][c0];
            }
#pragma unroll
            for (int im = 0; im < 4; im++)
#pragma unroll
                for (int jn = 0; jn < 4; jn++) mma_tf32(acc[im][jn], a[im], b[jn]);
        }
    }

    const int bb = bh / Hv, h = bh % Hv;
#pragma unroll
    for (int jn = 0; jn < 4; jn++) {
        const int d = wn + (jn << 3) + (t << 1);
#pragma unroll
        for (int im = 0; im < 4; im++) {
            int m = m0 + wm + (im << 4) + g;
            if (m < Nv)
                *(float2*)&g_O[((size_t)bb * Nv + m) * Cv + h * HDv + d] =
                    make_float2(f2tf_f(acc[im][jn][0]), f2tf_f(acc[im][jn][1]));
            if (m + 8 < Nv)
                *(float2*)&g_O[((size_t)bb * Nv + m + 8) * Cv + h * HDv + d] =
                    make_float2(f2tf_f(acc[im][jn][2]), f2tf_f(acc[im][jn][3]));
        }
    }
}

// ---------------------------------------------------------------------------
// Kernel 5: out = O (9216x768, pre-rounded) @ Wproj^T + bproj
// ---------------------------------------------------------------------------
__global__ __launch_bounds__(256) void proj_gemm_kernel(const float* __restrict__ W,
                                                        const float* __restrict__ bias,
                                                        float* __restrict__ Y) {
    __shared__ uint32_t As[128][PAD];
    __shared__ uint32_t Bs[128][PAD];
    const int tid = threadIdx.x;
    const int wid = tid >> 5, lane = tid & 31;
    const int wm = (wid >> 2) << 6;
    const int wn = (wid & 3) << 5;
    const int g = lane >> 2, t = lane & 3;
    const int m0 = blockIdx.y << 7, n0 = blockIdx.x << 7;
    const int lr = tid >> 3, lc = (tid & 7) << 2;
    const int K = Cv;
    const float* __restrict__ X = g_O;

    float acc[4][4][4];
#pragma unroll
    for (int im = 0; im < 4; im++)
#pragma unroll
        for (int jn = 0; jn < 4; jn++)
#pragma unroll
            for (int r = 0; r < 4; r++) acc[im][jn][r] = 0.f;

    uint4 pa[4];
    float4 pb[4];
#pragma unroll
    for (int i = 0; i < 4; i++) {
        pa[i] = *(const uint4*)(X + (size_t)(m0 + lr + 32 * i) * K + lc);
        pb[i] = *(const float4*)(W + (size_t)(n0 + lr + 32 * i) * K + lc);
    }

    for (int kb = 0; kb < K; kb += 32) {
        __syncthreads();
#pragma unroll
        for (int i = 0; i < 4; i++) {
            *(uint4*)&As[lr + 32 * i][lc] = pa[i];
            *(uint4*)&Bs[lr + 32 * i][lc] = make_uint4(f2tf(pb[i].x), f2tf(pb[i].y), f2tf(pb[i].z), f2tf(pb[i].w));
        }
        __syncthreads();
        if (kb + 32 < K) {
#pragma unroll
            for (int i = 0; i < 4; i++) {
                pa[i] = *(const uint4*)(X + (size_t)(m0 + lr + 32 * i) * K + kb + 32 + lc);
                pb[i] = *(const float4*)(W + (size_t)(n0 + lr + 32 * i) * K + kb + 32 + lc);
            }
        }
#pragma unroll
        for (int k8 = 0; k8 < 32; k8 += 8) {
            uint32_t a[4][4], b[4][2];
#pragma unroll
            for (int im = 0; im < 4; im++) {
                int r0 = wm + (im << 4) + g;
                a[im][0] = As[r0][k8 + t];     a[im][1] = As[r0 + 8][k8 + t];
                a[im][2] = As[r0][k8 + t + 4]; a[im][3] = As[r0 + 8][k8 + t + 4];
            }
#pragma unroll
            for (int jn = 0; jn < 4; jn++) {
                int c0 = wn + (jn << 3) + g;
                b[jn][0] = Bs[c0][k8 + t];
                b[jn][1] = Bs[c0][k8 + t + 4];
            }
#pragma unroll
            for (int im = 0; im < 4; im++)
#pragma unroll
                for (int jn = 0; jn < 4; jn++) mma_tf32(acc[im][jn], a[im], b[jn]);
        }
    }

#pragma unroll
    for (int jn = 0; jn < 4; jn++) {
        const int col = n0 + wn + (jn << 3) + (t << 1);
        const float2 bi = *(const float2*)&bias[col];
#pragma unroll
        for (int im = 0; im < 4; im++) {
            int r = m0 + wm + (im << 4) + g;
            *(float2*)&Y[(size_t)r * Cv + col] =
                make_float2(acc[im][jn][0] + bi.x, acc[im][jn][1] + bi.y);
            *(float2*)&Y[(size_t)(r + 8) * Cv + col] =
                make_float2(acc[im][jn][2] + bi.x, acc[im][jn][3] + bi.y);
        }
    }
}

extern "C" void kernel_launch(void* const* d_in, const int* in_sizes, int n_in,
                              void* d_out, int out_size) {
    const float* x     = (const float*)d_in[0];
    const float* Wqkv  = (const float*)d_in[1];
    const float* Wl    = (const float*)d_in[2];
    const float* bl    = (const float*)d_in[3];
    const float* Ww    = (const float*)d_in[4];
    const float* bw    = (const float*)d_in[5];
    const float* Wproj = (const float*)d_in[6];
    const float* bproj = (const float*)d_in[7];
    float* out = (float*)d_out;

    qkv_gemm_kernel<<<dim3(3 * Cv / 128, MROWS / 128), 256>>>(x, Wqkv);
    scores_gemm_kernel<<<dim3(5, 5, BH), 256>>>();
    mix_softmax_kernel<<<dim3(Nv, Bv), Nv>>>(Wl, bl, Ww, bw);
    pv_gemm_kernel<<<dim3(BH, 5), 128>>>();
    proj_gemm_kernel<<<dim3(Cv / 128, MROWS / 128), 256>>>(Wproj, bproj, out);
}

// round 11
// speedup vs baseline: 2.5943x; 1.0956x over previous
#include <cuda_runtime.h>
#include <cstdint>

// Problem constants
#define Bv 16
#define Nv 576
#define Cv 768
#define Hv 12
#define HDv 64
#define BH (Bv*Hv)            // 192
#define MROWS (Bv*Nv)         // 9216

// Scratch (device globals). All GEMM operands in gmem are PRE-ROUNDED tf32.
__device__ float g_xt[MROWS * Cv];          // x, tf32-rounded
__device__ float g_wqkvt[3 * Cv * Cv];      // Wqkv, tf32-rounded
__device__ float g_wprojt[Cv * Cv];         // Wproj, tf32-rounded
__device__ float g_q[BH * Nv * HDv];        // (b,h,n,d), pre-scaled 0.125, rounded
__device__ float g_k[BH * Nv * HDv];
__device__ float g_v[BH * Nv * HDv];
__device__ float g_S[(size_t)BH * Nv * Nv]; // scores -> mixed probs, rounded
__device__ float g_O[MROWS * Cv];           // rounded

__device__ __forceinline__ uint32_t f2tf(float f) {
    uint32_t u;
    asm("cvt.rna.tf32.f32 %0, %1;" : "=r"(u) : "f"(f));
    return u;
}
__device__ __forceinline__ float f2tf_f(float f) { return __uint_as_float(f2tf(f)); }

__device__ __forceinline__ void mma_tf32(float* c, const uint32_t* a, const uint32_t* b) {
    asm volatile(
        "mma.sync.aligned.m16n8k8.row.col.f32.tf32.tf32.f32 "
        "{%0,%1,%2,%3}, {%4,%5,%6,%7}, {%8,%9}, {%0,%1,%2,%3};\n"
        : "+f"(c[0]), "+f"(c[1]), "+f"(c[2]), "+f"(c[3])
        : "r"(a[0]), "r"(a[1]), "r"(a[2]), "r"(a[3]), "r"(b[0]), "r"(b[1]));
}

__device__ __forceinline__ uint32_t smem_u32(const void* p) {
    return (uint32_t)__cvta_generic_to_shared(p);
}
__device__ __forceinline__ void cpa16(uint32_t dst, const void* src) {
    asm volatile("cp.async.cg.shared.global [%0], [%1], 16;\n" :: "r"(dst), "l"(src));
}
__device__ __forceinline__ void cp_commit() { asm volatile("cp.async.commit_group;\n"); }
template <int N> __device__ __forceinline__ void cp_wait() {
    asm volatile("cp.async.wait_group %0;\n" :: "n"(N));
}

#define PAD 36    // [row][k] stride: frag reads -> 4g+t bank bijection
#define PADK 68   // [row][k] stride for K=64 single-shot tiles
#define PADB 72   // [k][n] stride: frag reads -> 8t+g bank bijection

#define QKV_SMEM  (3 * 2 * 128 * PAD * 4)                     // 110592
#define SCORE_SMEM (2 * 128 * PADK * 4)                       // 69632
#define PV_SMEM   ((3 * 128 * PAD + 3 * 32 * PADB) * 4)       // 82944
#define PROJ_SMEM (3 * 2 * 128 * PAD * 4)                     // 110592

// ---------------------------------------------------------------------------
// Kernel 0: pre-round x, Wqkv, Wproj to tf32 (float4-vectorized)
// ---------------------------------------------------------------------------
#define NX4 (MROWS * Cv / 4)
#define NW4 (3 * Cv * Cv / 4)
#define NP4 (Cv * Cv / 4)
__global__ __launch_bounds__(256) void cvt_inputs_kernel(const float* __restrict__ x,
                                                         const float* __restrict__ wqkv,
                                                         const float* __restrict__ wproj) {
    int i = blockIdx.x * blockDim.x + threadIdx.x;
    if (i < NX4) {
        float4 v = ((const float4*)x)[i];
        ((uint4*)g_xt)[i] = make_uint4(f2tf(v.x), f2tf(v.y), f2tf(v.z), f2tf(v.w));
    } else if (i < NX4 + NW4) {
        int j = i - NX4;
        float4 v = ((const float4*)wqkv)[j];
        ((uint4*)g_wqkvt)[j] = make_uint4(f2tf(v.x), f2tf(v.y), f2tf(v.z), f2tf(v.w));
    } else if (i < NX4 + NW4 + NP4) {
        int j = i - NX4 - NW4;
        float4 v = ((const float4*)wproj)[j];
        ((uint4*)g_wprojt)[j] = make_uint4(f2tf(v.x), f2tf(v.y), f2tf(v.z), f2tf(v.w));
    }
}

// ---------------------------------------------------------------------------
// Kernel 1: qkv = xt @ WqkvT^T  -> g_q(*0.125)/g_k/g_v.  3-stage cp.async.
// 128x128x32 tile, 256 threads, warp grid 2x4, warp tile 64x32.
// ---------------------------------------------------------------------------
__global__ void __launch_bounds__(256, 2) qkv_gemm_kernel() {
    extern __shared__ uint32_t sm[];
    uint32_t* As = sm;                      // 3 stages x 128 x PAD
    uint32_t* Bs = sm + 3 * 128 * PAD;
    const int tid = threadIdx.x;
    const int wid = tid >> 5, lane = tid & 31;
    const int wm = (wid >> 2) << 6, wn = (wid & 3) << 5;
    const int g = lane >> 2, t = lane & 3;
    const int m0 = blockIdx.y << 7, n0 = blockIdx.x << 7;
    const int lr = tid >> 3, lc = (tid & 7) << 2;
    const int K = Cv;
    const float* X = g_xt;
    const float* W = g_wqkvt;
    const uint32_t baseA = smem_u32(As), baseB = smem_u32(Bs);

    float acc[4][4][4];
#pragma unroll
    for (int im = 0; im < 4; im++)
#pragma unroll
        for (int jn = 0; jn < 4; jn++)
#pragma unroll
            for (int r = 0; r < 4; r++) acc[im][jn][r] = 0.f;

#define QKV_ISSUE(s, kb)                                                             \
    do {                                                                             \
        uint32_t sA = baseA + (uint32_t)((s) * 128 * PAD) * 4;                       \
        uint32_t sB = baseB + (uint32_t)((s) * 128 * PAD) * 4;                       \
        _Pragma("unroll") for (int ci = 0; ci < 4; ci++) {                           \
            cpa16(sA + (uint32_t)((lr + 32 * ci) * PAD + lc) * 4,                    \
                  X + (size_t)(m0 + lr + 32 * ci) * K + (kb) + lc);                  \
            cpa16(sB + (uint32_t)((lr + 32 * ci) * PAD + lc) * 4,                    \
                  W + (size_t)(n0 + lr + 32 * ci) * K + (kb) + lc);                  \
        }                                                                            \
        cp_commit();                                                                 \
    } while (0)

    QKV_ISSUE(0, 0);
    QKV_ISSUE(1, 32);
    const int nk = K / 32;
    for (int i = 0; i < nk; i++) {
        cp_wait<1>();
        __syncthreads();
        if (i + 2 < nk) QKV_ISSUE((i + 2) % 3, (i + 2) * 32);
        else cp_commit();   // empty group keeps wait-depth arithmetic exact
        const uint32_t* Ac = As + (i % 3) * 128 * PAD;
        const uint32_t* Bc = Bs + (i % 3) * 128 * PAD;
#pragma unroll
        for (int k8 = 0; k8 < 32; k8 += 8) {
            uint32_t a[4][4], b[4][2];
#pragma unroll
            for (int im = 0; im < 4; im++) {
                int r0 = wm + (im << 4) + g;
                a[im][0] = Ac[r0 * PAD + k8 + t];       a[im][1] = Ac[(r0 + 8) * PAD + k8 + t];
                a[im][2] = Ac[r0 * PAD + k8 + t + 4];   a[im][3] = Ac[(r0 + 8) * PAD + k8 + t + 4];
            }
#pragma unroll
            for (int jn = 0; jn < 4; jn++) {
                int c0 = wn + (jn << 3) + g;
                b[jn][0] = Bc[c0 * PAD + k8 + t];
                b[jn][1] = Bc[c0 * PAD + k8 + t + 4];
            }
#pragma unroll
            for (int im = 0; im < 4; im++)
#pragma unroll
                for (int jn = 0; jn < 4; jn++) mma_tf32(acc[im][jn], a[im], b[jn]);
        }
    }

    // epilogue: tf32-round + scatter
#pragma unroll
    for (int jn = 0; jn < 4; jn++) {
        const int col = n0 + wn + (jn << 3) + (t << 1);
        const int tsel = col / Cv;
        const int rem = col % Cv;
        const int h = rem >> 6, d = rem & 63;
        float* dst = (tsel == 0) ? g_q : (tsel == 1) ? g_k : g_v;
        const float scale = (tsel == 0) ? 0.125f : 1.0f;
#pragma unroll
        for (int im = 0; im < 4; im++) {
            int r = m0 + wm + (im << 4) + g;
            {
                int bb = r / Nv, n = r % Nv;
                *(float2*)&dst[(((size_t)bb * Hv + h) * Nv + n) * HDv + d] =
                    make_float2(f2tf_f(acc[im][jn][0] * scale), f2tf_f(acc[im][jn][1] * scale));
            }
            int r2 = r + 8;
            {
                int bb = r2 / Nv, n = r2 % Nv;
                *(float2*)&dst[(((size_t)bb * Hv + h) * Nv + n) * HDv + d] =
                    make_float2(f2tf_f(acc[im][jn][2] * scale), f2tf_f(acc[im][jn][3] * scale));
            }
        }
    }
}

// ---------------------------------------------------------------------------
// Kernel 2: S[bh] = q (576x64) @ k^T.  K=64: single-shot load, then all MMAs.
// ---------------------------------------------------------------------------
__global__ void __launch_bounds__(256, 2) scores_gemm_kernel() {
    extern __shared__ uint32_t sm[];
    uint32_t* As = sm;                 // 128 x PADK
    uint32_t* Bs = sm + 128 * PADK;
    const int tid = threadIdx.x;
    const int wid = tid >> 5, lane = tid & 31;
    const int wm = (wid >> 2) << 6, wn = (wid & 3) << 5;
    const int g = lane >> 2, t = lane & 3;
    const int bh = blockIdx.z;
    const int m0 = blockIdx.x << 7, n0 = blockIdx.y << 7;
    const int sr = tid >> 4, sc = (tid & 15) << 2;
    const float* X = g_q + (size_t)bh * Nv * HDv;
    const float* W = g_k + (size_t)bh * Nv * HDv;
    const uint32_t baseA = smem_u32(As), baseB = smem_u32(Bs);

#pragma unroll
    for (int i = 0; i < 8; i++) {
        int row = sr + 16 * i;
        int rA = min(m0 + row, Nv - 1);
        int rB = min(n0 + row, Nv - 1);
        cpa16(baseA + (uint32_t)(row * PADK + sc) * 4, X + (size_t)rA * HDv + sc);
        cpa16(baseB + (uint32_t)(row * PADK + sc) * 4, W + (size_t)rB * HDv + sc);
    }
    cp_commit();

    float acc[4][4][4];
#pragma unroll
    for (int im = 0; im < 4; im++)
#pragma unroll
        for (int jn = 0; jn < 4; jn++)
#pragma unroll
            for (int r = 0; r < 4; r++) acc[im][jn][r] = 0.f;

    cp_wait<0>();
    __syncthreads();

#pragma unroll
    for (int k8 = 0; k8 < HDv; k8 += 8) {
        uint32_t a[4][4], b[4][2];
#pragma unroll
        for (int im = 0; im < 4; im++) {
            int r0 = wm + (im << 4) + g;
            a[im][0] = As[r0 * PADK + k8 + t];       a[im][1] = As[(r0 + 8) * PADK + k8 + t];
            a[im][2] = As[r0 * PADK + k8 + t + 4];   a[im][3] = As[(r0 + 8) * PADK + k8 + t + 4];
        }
#pragma unroll
        for (int jn = 0; jn < 4; jn++) {
            int c0 = wn + (jn << 3) + g;
            b[jn][0] = Bs[c0 * PADK + k8 + t];
            b[jn][1] = Bs[c0 * PADK + k8 + t + 4];
        }
#pragma unroll
        for (int im = 0; im < 4; im++)
#pragma unroll
            for (int jn = 0; jn < 4; jn++) mma_tf32(acc[im][jn], a[im], b[jn]);
    }

    float* Sp = g_S + (size_t)bh * Nv * Nv;
#pragma unroll
    for (int jn = 0; jn < 4; jn++) {
        const int col = n0 + wn + (jn << 3) + (t << 1);
        if (col >= Nv) continue;
#pragma unroll
        for (int im = 0; im < 4; im++) {
            int r = m0 + wm + (im << 4) + g;
            if (r < Nv)
                *(float2*)&Sp[(size_t)r * Nv + col] =
                    make_float2(f2tf_f(acc[im][jn][0]), f2tf_f(acc[im][jn][1]));
            if (r + 8 < Nv)
                *(float2*)&Sp[(size_t)(r + 8) * Nv + col] =
                    make_float2(f2tf_f(acc[im][jn][2]), f2tf_f(acc[im][jn][3]));
        }
    }
}

// ---------------------------------------------------------------------------
// Kernel 3: per (b,m): pre-mix -> softmax -> post-mix, in place (round on store)
// ---------------------------------------------------------------------------
__global__ __launch_bounds__(576) void mix_softmax_kernel(const float* __restrict__ Wl,
                                                          const float* __restrict__ bl,
                                                          const float* __restrict__ Ww,
                                                          const float* __restrict__ bw) {
    __shared__ float Ls[Hv][Nv];
    __shared__ float wl_s[Hv * Hv], ww_s[Hv * Hv], bl_s[Hv], bw_s[Hv];
    const int m = blockIdx.x;
    const int b = blockIdx.y;
    const int tid = threadIdx.x;

    if (tid < Hv * Hv) { wl_s[tid] = Wl[tid]; ww_s[tid] = Ww[tid]; }
    if (tid < Hv) { bl_s[tid] = bl[tid]; bw_s[tid] = bw[tid]; }
    __syncthreads();

    float L[Hv];
#pragma unroll
    for (int g = 0; g < Hv; g++) L[g] = bl_s[g];
#pragma unroll
    for (int h = 0; h < Hv; h++) {
        float sval = g_S[(((size_t)b * Hv + h) * Nv + m) * Nv + tid];
#pragma unroll
        for (int g = 0; g < Hv; g++) L[g] += wl_s[g * Hv + h] * sval;
    }
#pragma unroll
    for (int g = 0; g < Hv; g++) Ls[g][tid] = L[g];
    __syncthreads();

    const int w = tid >> 5, lane = tid & 31;
    if (w < Hv) {
        float mx = -1e30f;
        for (int n = lane; n < Nv; n += 32) mx = fmaxf(mx, Ls[w][n]);
#pragma unroll
        for (int o = 16; o; o >>= 1) mx = fmaxf(mx, __shfl_xor_sync(0xffffffffu, mx, o));
        float s = 0.f;
        for (int n = lane; n < Nv; n += 32) {
            float e = __expf(Ls[w][n] - mx);
            Ls[w][n] = e;
            s += e;
        }
#pragma unroll
        for (int o = 16; o; o >>= 1) s += __shfl_xor_sync(0xffffffffu, s, o);
        float inv = 1.f / s;
        for (int n = lane; n < Nv; n += 32) Ls[w][n] *= inv;
    }
    __syncthreads();

    float p[Hv];
#pragma unroll
    for (int h = 0; h < Hv; h++) p[h] = Ls[h][tid];
#pragma unroll
    for (int g = 0; g < Hv; g++) {
        float a = bw_s[g];
#pragma unroll
        for (int h = 0; h < Hv; h++) a += ww_s[g * Hv + h] * p[h];
        g_S[(((size_t)b * Hv + g) * Nv + m) * Nv + tid] = f2tf_f(a);
    }
}

// ---------------------------------------------------------------------------
// Kernel 4: O[bh] = P'[bh] (576x576) @ V[bh] (576x64).  3-stage cp.async.
// 128x64x32 tile, 256 threads, warp grid 4x2, warp tile 32x32.
// ---------------------------------------------------------------------------
__global__ void __launch_bounds__(256, 2) pv_gemm_kernel() {
    extern __shared__ uint32_t sm[];
    uint32_t* As = sm;                      // 3 stages x 128 x PAD
    uint32_t* Vs = sm + 3 * 128 * PAD;      // 3 stages x 32 x PADB
    const int tid = threadIdx.x;
    const int wid = tid >> 5, lane = tid & 31;
    const int wm = (wid >> 1) << 5;         // 0,32,64,96
    const int wn = (wid & 1) << 5;          // 0,32
    const int g = lane >> 2, t = lane & 3;
    const int bh = blockIdx.x;
    const int m0 = blockIdx.y << 7;
    const int lr = tid >> 3, lc = (tid & 7) << 2;
    const int vr = tid >> 4, vc = (tid & 15) << 2;
    const float* A = g_S + (size_t)bh * Nv * Nv;
    const float* V = g_v + (size_t)bh * Nv * HDv;
    const uint32_t baseA = smem_u32(As), baseV = smem_u32(Vs);

    int rA[4];
#pragma unroll
    for (int i = 0; i < 4; i++) rA[i] = min(m0 + lr + 32 * i, Nv - 1);

    float acc[2][4][4];
#pragma unroll
    for (int im = 0; im < 2; im++)
#pragma unroll
        for (int jn = 0; jn < 4; jn++)
#pragma unroll
            for (int r = 0; r < 4; r++) acc[im][jn][r] = 0.f;

#define PV_ISSUE(s, kb)                                                              \
    do {                                                                             \
        uint32_t sA = baseA + (uint32_t)((s) * 128 * PAD) * 4;                       \
        uint32_t sV = baseV + (uint32_t)((s) * 32 * PADB) * 4;                       \
        _Pragma("unroll") for (int ci = 0; ci < 4; ci++)                             \
            cpa16(sA + (uint32_t)((lr + 32 * ci) * PAD + lc) * 4,                    \
                  A + (size_t)rA[ci] * Nv + (kb) + lc);                              \
        _Pragma("unroll") for (int ci = 0; ci < 2; ci++)                             \
            cpa16(sV + (uint32_t)((vr + 16 * ci) * PADB + vc) * 4,                   \
                  V + (size_t)((kb) + vr + 16 * ci) * HDv + vc);                     \
        cp_commit();                                                                 \
    } while (0)

    PV_ISSUE(0, 0);
    PV_ISSUE(1, 32);
    const int nk = Nv / 32;
    for (int i = 0; i < nk; i++) {
        cp_wait<1>();
        __syncthreads();
        if (i + 2 < nk) PV_ISSUE((i + 2) % 3, (i + 2) * 32);
        else cp_commit();   // empty group keeps wait-depth arithmetic exact
        const uint32_t* Ac = As + (i % 3) * 128 * PAD;
        const uint32_t* Vc = Vs + (i % 3) * 32 * PADB;
#pragma unroll
        for (int k8 = 0; k8 < 32; k8 += 8) {
            uint32_t a[2][4], b[4][2];
#pragma unroll
            for (int im = 0; im < 2; im++) {
                int r0 = wm + (im << 4) + g;
                a[im][0] = Ac[r0 * PAD + k8 + t];       a[im][1] = Ac[(r0 + 8) * PAD + k8 + t];
                a[im][2] = Ac[r0 * PAD + k8 + t + 4];   a[im][3] = Ac[(r0 + 8) * PAD + k8 + t + 4];
            }
#pragma unroll
            for (int jn = 0; jn < 4; jn++) {
                int c0 = wn + (jn << 3) + g;
                b[jn][0] = Vc[(k8 + t) * PADB + c0];
                b[jn][1] = Vc[(k8 + t + 4) * PADB + c0];
            }
#pragma unroll
            for (int im = 0; im < 2; im++)
#pragma unroll
                for (int jn = 0; jn < 4; jn++) mma_tf32(acc[im][jn], a[im], b[jn]);
        }
    }

    const int bb = bh / Hv, h = bh % Hv;
#pragma unroll
    for (int jn = 0; jn < 4; jn++) {
        const int d = wn + (jn << 3) + (t << 1);
#pragma unroll
        for (int im = 0; im < 2; im++) {
            int m = m0 + wm + (im << 4) + g;
            if (m < Nv)
                *(float2*)&g_O[((size_t)bb * Nv + m) * Cv + h * HDv + d] =
                    make_float2(f2tf_f(acc[im][jn][0]), f2tf_f(acc[im][jn][1]));
            if (m + 8 < Nv)
                *(float2*)&g_O[((size_t)bb * Nv + m + 8) * Cv + h * HDv + d] =
                    make_float2(f2tf_f(acc[im][jn][2]), f2tf_f(acc[im][jn][3]));
        }
    }
}

// ---------------------------------------------------------------------------
// Kernel 5: out = O (pre-rounded) @ WprojT^T + bproj.  3-stage cp.async.
// ---------------------------------------------------------------------------
__global__ void __launch_bounds__(256, 2) proj_gemm_kernel(const float* __restrict__ bias,
                                                           float* __restrict__ Y) {
    extern __shared__ uint32_t sm[];
    uint32_t* As = sm;
    uint32_t* Bs = sm + 3 * 128 * PAD;
    const int tid = threadIdx.x;
    const int wid = tid >> 5, lane = tid & 31;
    const int wm = (wid >> 2) << 6, wn = (wid & 3) << 5;
    const int g = lane >> 2, t = lane & 3;
    const int m0 = blockIdx.y << 7, n0 = blockIdx.x << 7;
    const int lr = tid >> 3, lc = (tid & 7) << 2;
    const int K = Cv;
    const float* X = g_O;
    const float* W = g_wprojt;
    const uint32_t baseA = smem_u32(As), baseB = smem_u32(Bs);

    float acc[4][4][4];
#pragma unroll
    for (int im = 0; im < 4; im++)
#pragma unroll
        for (int jn = 0; jn < 4; jn++)
#pragma unroll
            for (int r = 0; r < 4; r++) acc[im][jn][r] = 0.f;

#define PROJ_ISSUE(s, kb)                                                            \
    do {                                                                             \
        uint32_t sA = baseA + (uint32_t)((s) * 128 * PAD) * 4;                       \
        uint32_t sB = baseB + (uint32_t)((s) * 128 * PAD) * 4;                       \
        _Pragma("unroll") for (int ci = 0; ci < 4; ci++) {                           \
            cpa16(sA + (uint32_t)((lr + 32 * ci) * PAD + lc) * 4,                    \
                  X + (size_t)(m0 + lr + 32 * ci) * K + (kb) + lc);                  \
            cpa16(sB + (uint32_t)((lr + 32 * ci) * PAD + lc) * 4,                    \
                  W + (size_t)(n0 + lr + 32 * ci) * K + (kb) + lc);                  \
        }                                                                            \
        cp_commit();                                                                 \
    } while (0)

    PROJ_ISSUE(0, 0);
    PROJ_ISSUE(1, 32);
    const int nk = K / 32;
    for (int i = 0; i < nk; i++) {
        cp_wait<1>();
        __syncthreads();
        if (i + 2 < nk) PROJ_ISSUE((i + 2) % 3, (i + 2) * 32);
        else cp_commit();   // empty group keeps wait-depth arithmetic exact
        const uint32_t* Ac = As + (i % 3) * 128 * PAD;
        const uint32_t* Bc = Bs + (i % 3) * 128 * PAD;
#pragma unroll
        for (int k8 = 0; k8 < 32; k8 += 8) {
            uint32_t a[4][4], b[4][2];
#pragma unroll
            for (int im = 0; im < 4; im++) {
                int r0 = wm + (im << 4) + g;
                a[im][0] = Ac[r0 * PAD + k8 + t];       a[im][1] = Ac[(r0 + 8) * PAD + k8 + t];
                a[im][2] = Ac[r0 * PAD + k8 + t + 4];   a[im][3] = Ac[(r0 + 8) * PAD + k8 + t + 4];
            }
#pragma unroll
            for (int jn = 0; jn < 4; jn++) {
                int c0 = wn + (jn << 3) + g;
                b[jn][0] = Bc[c0 * PAD + k8 + t];
                b[jn][1] = Bc[c0 * PAD + k8 + t + 4];
            }
#pragma unroll
            for (int im = 0; im < 4; im++)
#pragma unroll
                for (int jn = 0; jn < 4; jn++) mma_tf32(acc[im][jn], a[im], b[jn]);
        }
    }

#pragma unroll
    for (int jn = 0; jn < 4; jn++) {
        const int col = n0 + wn + (jn << 3) + (t << 1);
        const float2 bi = *(const float2*)&bias[col];
#pragma unroll
        for (int im = 0; im < 4; im++) {
            int r = m0 + wm + (im << 4) + g;
            *(float2*)&Y[(size_t)r * Cv + col] =
                make_float2(acc[im][jn][0] + bi.x, acc[im][jn][1] + bi.y);
            *(float2*)&Y[(size_t)(r + 8) * Cv + col] =
                make_float2(acc[im][jn][2] + bi.x, acc[im][jn][3] + bi.y);
        }
    }
}

extern "C" void kernel_launch(void* const* d_in, const int* in_sizes, int n_in,
                              void* d_out, int out_size) {
    const float* x     = (const float*)d_in[0];
    const float* Wqkv  = (const float*)d_in[1];
    const float* Wl    = (const float*)d_in[2];
    const float* bl    = (const float*)d_in[3];
    const float* Ww    = (const float*)d_in[4];
    const float* bw    = (const float*)d_in[5];
    const float* Wproj = (const float*)d_in[6];
    const float* bproj = (const float*)d_in[7];
    float* out = (float*)d_out;

    // allow >48KB dynamic smem (idempotent host calls; not allocations)
    cudaFuncSetAttribute(qkv_gemm_kernel,    cudaFuncAttributeMaxDynamicSharedMemorySize, QKV_SMEM);
    cudaFuncSetAttribute(scores_gemm_kernel, cudaFuncAttributeMaxDynamicSharedMemorySize, SCORE_SMEM);
    cudaFuncSetAttribute(pv_gemm_kernel,     cudaFuncAttributeMaxDynamicSharedMemorySize, PV_SMEM);
    cudaFuncSetAttribute(proj_gemm_kernel,   cudaFuncAttributeMaxDynamicSharedMemorySize, PROJ_SMEM);

    cvt_inputs_kernel<<<(NX4 + NW4 + NP4 + 255) / 256, 256>>>(x, Wqkv, Wproj);
    qkv_gemm_kernel<<<dim3(3 * Cv / 128, MROWS / 128), 256, QKV_SMEM>>>();
    scores_gemm_kernel<<<dim3(5, 5, BH), 256, SCORE_SMEM>>>();
    mix_softmax_kernel<<<dim3(Nv, Bv), Nv>>>(Wl, bl, Ww, bw);
    pv_gemm_kernel<<<dim3(BH, 5), 256, PV_SMEM>>>();
    proj_gemm_kernel<<<dim3(Cv / 128, MROWS / 128), 256, PROJ_SMEM>>>(bproj, out);
}